// round 12
// baseline (speedup 1.0000x reference)
#include <cuda_runtime.h>
#include <cuda_fp16.h>
#include <math.h>
#include <stdint.h>

// ---------------- problem constants ----------------
#define BB 2
#define LL 4096
#define DM 1024
#define DIN 2048
#define NH 32
#define HD 64
#define DS 128
#define CHUNKSZ 256
#define NCHK 16
#define CONVDIM 2304        // DIN + 2*DS
#define DPROJ 4384          // 2*DIN + 2*DS + NH
#define NTOK (BB*LL)        // 8192
#define EPSV 1e-5f

// ---------------- scratch (device globals; no allocs allowed) ----------------
__device__ __half g_xh[(size_t)NTOK*DM];                // rmsnorm output (half)
__device__ float g_zxbcdt[(size_t)NTOK*DPROJ];
__device__ float g_xBCc[(size_t)NTOK*CONVDIM];
__device__ float g_dtv[(size_t)NTOK*NH];
__device__ float g_Acum[(size_t)BB*NCHK*NH*CHUNKSZ];
__device__ __half g_Gh[(size_t)BB*NCHK*CHUNKSZ*CHUNKSZ];  // G in half (4.2 MB)
__device__ float g_states[(size_t)BB*NCHK*NH*HD*DS];
__device__ float g_prevS[(size_t)BB*NCHK*NH*HD*DS];
__device__ float g_ydiag[(size_t)NTOK*DIN];             // also final y (in place)
__device__ __half g_ygh[(size_t)NTOK*DIN];              // gatenorm output (half)
__device__ __half g_wAh[(size_t)DM*DPROJ];              // half in_proj_w
__device__ __half g_wBh[(size_t)DIN*DM];                // half out_proj_w

__device__ __forceinline__ float siluf(float x){ return x / (1.f + __expf(-x)); }

__device__ __forceinline__ uint32_t smem_u32(const void* p){
    uint32_t a;
    asm("{ .reg .u64 t; cvta.to.shared.u64 t, %1; cvt.u32.u64 %0, t; }" : "=r"(a) : "l"(p));
    return a;
}

__device__ __forceinline__ void cpa16(uint32_t dst, const void* src, bool pred){
    int sz = pred ? 16 : 0;
    asm volatile("cp.async.cg.shared.global [%0], [%1], 16, %2;" :: "r"(dst), "l"(src), "r"(sz));
}

#define CP_COMMIT() asm volatile("cp.async.commit_group;")
#define CP_WAIT2()  asm volatile("cp.async.wait_group 2;")

#define LDSM4(r0,r1,r2,r3,addr) \
    asm volatile("ldmatrix.sync.aligned.m8n8.x4.shared.b16 {%0,%1,%2,%3}, [%4];" \
        : "=r"(r0),"=r"(r1),"=r"(r2),"=r"(r3) : "r"(addr))

#define LDSM4T(r0,r1,r2,r3,addr) \
    asm volatile("ldmatrix.sync.aligned.m8n8.x4.trans.shared.b16 {%0,%1,%2,%3}, [%4];" \
        : "=r"(r0),"=r"(r1),"=r"(r2),"=r"(r3) : "r"(addr))

#define MMA_F16(c, a, b) \
    asm volatile("mma.sync.aligned.m16n8k16.row.col.f32.f16.f16.f32 " \
        "{%0,%1,%2,%3}, {%4,%5,%6,%7}, {%8,%9}, {%0,%1,%2,%3};" \
        : "+f"((c)[0]),"+f"((c)[1]),"+f"((c)[2]),"+f"((c)[3]) \
        : "r"((a)[0]),"r"((a)[1]),"r"((a)[2]),"r"((a)[3]), "r"((b)[0]),"r"((b)[1]))

// ---------------- K0: convert fp32 array to half ----------------
__global__ void f2h_kernel(const float* __restrict__ in, __half* __restrict__ out, int n4){
    int i = blockIdx.x*blockDim.x + threadIdx.x;
    if (i >= n4) return;
    float4 v = ((const float4*)in)[i];
    __half2 hs[2];
    hs[0] = __floats2half2_rn(v.x, v.y);
    hs[1] = __floats2half2_rn(v.z, v.w);
    *(uint2*)(out + (size_t)i*4) = *(uint2*)hs;
}

// ---------------- K1: RMSNorm over D_MODEL=1024 (half output) ----------------
__global__ __launch_bounds__(256) void rmsnorm_kernel(const float* __restrict__ x,
                                                      const float* __restrict__ w,
                                                      __half* __restrict__ out){
    int row = blockIdx.x;
    int t = threadIdx.x;
    float4 v = ((const float4*)(x + (size_t)row*DM))[t];
    float ss = v.x*v.x + v.y*v.y + v.z*v.z + v.w*v.w;
    __shared__ float red[8];
    for (int o=16;o>0;o>>=1) ss += __shfl_down_sync(0xffffffffu, ss, o);
    if ((t&31)==0) red[t>>5] = ss;
    __syncthreads();
    if (t < 32){
        float s2 = (t<8)? red[t] : 0.f;
        for (int o=4;o>0;o>>=1) s2 += __shfl_down_sync(0xffffffffu, s2, o);
        if (t==0) red[0] = s2;
    }
    __syncthreads();
    float scale = rsqrtf(red[0]/(float)DM + EPSV);
    float4 wv = ((const float4*)w)[t];
    __half2 hs[2];
    hs[0] = __floats2half2_rn(v.x*scale*wv.x, v.y*scale*wv.y);
    hs[1] = __floats2half2_rn(v.z*scale*wv.z, v.w*scale*wv.w);
    *(uint2*)(out + (size_t)row*DM + t*4) = *(uint2*)hs;
}

// ---------------- FP16 GEMM: 128x128 block, BK=32, 4-stage cp.async, 2 CTAs/SM ----
#define AH_STRIDE 40
#define BH_STRIDE 136
#define ASTG_H (128*AH_STRIDE)
#define BSTG_H (32*BH_STRIDE)
#define NSTAGE 4
#define GEMM_SMEM ((NSTAGE*(ASTG_H + BSTG_H))*2)

__global__ __launch_bounds__(256, 2) void h16gemm_kernel(int M, int N, int K,
                                                         const __half* __restrict__ A,
                                                         const __half* __restrict__ B,
                                                         const float* __restrict__ Cadd,
                                                         float* __restrict__ C){
    extern __shared__ __half hsmem[];
    __half* As = hsmem;
    __half* Bs = hsmem + NSTAGE*ASTG_H;
    uint32_t aSm = smem_u32(As);
    uint32_t bSm = smem_u32(Bs);

    int tid = threadIdx.x, lane = tid & 31, warp = tid >> 5;
    int warpM = warp & 1, warpN = warp >> 1;
    int gid = lane >> 2, tg = lane & 3;
    int lr = lane & 7, ls = lane >> 3;
    int rowBlk = blockIdx.y*128, colBase = blockIdx.x*128;

    int aRow = tid >> 1, aKc = (tid & 1)*16;
    int bK = tid >> 3, bN = (tid & 7)*16;

    const __half* Ag = A + (size_t)(rowBlk + aRow)*K + aKc;
    const __half* Bg = B + (size_t)bK*N + colBase + bN;
    bool p0 = (colBase + bN) < N;
    bool p1 = (colBase + bN + 8) < N;

    float acc[4][4][4] = {};
    int KT = K >> 5;

    #pragma unroll
    for (int s=0; s<3; s++){
        uint32_t ad = aSm + (uint32_t)(s*ASTG_H + aRow*AH_STRIDE + aKc)*2;
        const __half* ap = Ag + s*32;
        cpa16(ad, ap, true);
        cpa16(ad+16, ap+8, true);
        uint32_t bd = bSm + (uint32_t)(s*BSTG_H + bK*BH_STRIDE + bN)*2;
        const __half* bpp = Bg + (size_t)s*32*N;
        cpa16(bd, p0 ? bpp : B, p0);
        cpa16(bd+16, p1 ? bpp+8 : B, p1);
        CP_COMMIT();
    }

    for (int kt=0; kt<KT; kt++){
        int s = kt % NSTAGE;
        CP_WAIT2();
        __syncthreads();
        if (kt+3 < KT){
            int s2 = (kt+3) % NSTAGE;
            uint32_t ad = aSm + (uint32_t)(s2*ASTG_H + aRow*AH_STRIDE + aKc)*2;
            const __half* ap = Ag + (kt+3)*32;
            cpa16(ad, ap, true);
            cpa16(ad+16, ap+8, true);
            uint32_t bd = bSm + (uint32_t)(s2*BSTG_H + bK*BH_STRIDE + bN)*2;
            const __half* bpp = Bg + (size_t)(kt+3)*32*N;
            cpa16(bd, p0 ? bpp : B, p0);
            cpa16(bd+16, p1 ? bpp+8 : B, p1);
        }
        CP_COMMIT();

        uint32_t aBase = aSm + (uint32_t)(s*ASTG_H)*2;
        uint32_t bBase = bSm + (uint32_t)(s*BSTG_H)*2;
        #pragma unroll
        for (int kk=0; kk<2; kk++){
            int kc = kk*16;
            uint32_t af[4][4], bf[4][2];
            #pragma unroll
            for (int mt=0;mt<4;mt++){
                int m0 = warpM*64 + mt*16;
                uint32_t addr = aBase + (uint32_t)((m0 + (ls&1)*8 + lr)*AH_STRIDE + kc + (ls>>1)*8)*2;
                LDSM4(af[mt][0], af[mt][1], af[mt][2], af[mt][3], addr);
            }
            #pragma unroll
            for (int ntp=0;ntp<2;ntp++){
                int n0 = warpN*32 + ntp*16;
                uint32_t addr = bBase + (uint32_t)((kc + (ls&1)*8 + lr)*BH_STRIDE + n0 + (ls>>1)*8)*2;
                uint32_t r0,r1,r2,r3;
                LDSM4T(r0,r1,r2,r3, addr);
                bf[2*ntp][0]=r0; bf[2*ntp][1]=r1;
                bf[2*ntp+1][0]=r2; bf[2*ntp+1][1]=r3;
            }
            #pragma unroll
            for (int mt=0;mt<4;mt++)
                #pragma unroll
                for (int nt=0;nt<4;nt++)
                    MMA_F16(acc[mt][nt], af[mt], bf[nt]);
        }
    }

    #pragma unroll
    for (int mt=0;mt<4;mt++){
        int row0 = rowBlk + warpM*64 + mt*16 + gid;
        #pragma unroll
        for (int nt=0;nt<4;nt++){
            int col = colBase + warpN*32 + nt*8 + tg*2;
            if (col < N){
                float2 v0 = make_float2(acc[mt][nt][0], acc[mt][nt][1]);
                float2 v1 = make_float2(acc[mt][nt][2], acc[mt][nt][3]);
                if (Cadd){
                    float2 r0 = *(const float2*)(Cadd + (size_t)row0*N + col);
                    float2 r1 = *(const float2*)(Cadd + (size_t)(row0+8)*N + col);
                    v0.x += r0.x; v0.y += r0.y;
                    v1.x += r1.x; v1.y += r1.y;
                }
                *(float2*)(C + (size_t)row0*N + col) = v0;
                *(float2*)(C + (size_t)(row0+8)*N + col) = v1;
            }
        }
    }
}

// ---------------- K3: causal depthwise conv1d (k=4) + bias + SiLU ----------------
__global__ void conv_kernel(const float* __restrict__ zx, const float* __restrict__ cw,
                            const float* __restrict__ cb, float* __restrict__ out){
    int idx = blockIdx.x*blockDim.x + threadIdx.x;
    if (idx >= NTOK*CONVDIM) return;
    int c = idx % CONVDIM;
    int row = idx / CONVDIM;
    int l = row & (LL-1);
    float acc = cb[c];
    #pragma unroll
    for (int k=0;k<4;k++){
        int ls = l - 3 + k;
        if (ls >= 0) acc += zx[(size_t)(row-3+k)*DPROJ + DIN + c] * cw[c*4+k];
    }
    out[(size_t)row*CONVDIM + c] = siluf(acc);
}

// ---------------- K4: dt = softplus(dt_raw + dt_bias) ----------------
__global__ void dt_kernel(const float* __restrict__ zx, const float* __restrict__ dt_bias,
                          float* __restrict__ dtv){
    int idx = blockIdx.x*blockDim.x + threadIdx.x;
    if (idx >= NTOK*NH) return;
    int h = idx & (NH-1);
    int row = idx / NH;
    float x = zx[(size_t)row*DPROJ + (DIN + CONVDIM) + h] + dt_bias[h];
    dtv[idx] = (x > 20.f) ? x : log1pf(expf(x));
}

// ---------------- K5: per-(b,c,h) inclusive cumsum of dt*A over chunk ----------------
__global__ __launch_bounds__(256) void cumsum_kernel(const float* __restrict__ dtv,
                                                     const float* __restrict__ A_log,
                                                     float* __restrict__ Acum){
    int bid = blockIdx.x;
    int h = bid % NH; int c = (bid/NH) % NCHK; int b = bid/(NH*NCHK);
    int t = threadIdx.x;
    int row = b*LL + c*CHUNKSZ + t;
    float negA = -expf(A_log[h]);
    float v = dtv[(size_t)row*NH + h] * negA;
    __shared__ float sh[256];
    sh[t] = v; __syncthreads();
    for (int off=1; off<256; off<<=1){
        float add = (t >= off) ? sh[t-off] : 0.f;
        __syncthreads();
        sh[t] += add;
        __syncthreads();
    }
    Acum[(size_t)bid*CHUNKSZ + t] = sh[t];
}

// ---------------- K6: gmat fp16 MMA: G = C·B^T per (b,c), half output ----------
#define GM_SMEM (2*128*136*2)
__global__ __launch_bounds__(256) void gmat_h_kernel(const float* __restrict__ xbc,
                                                     __half* __restrict__ Gh){
    extern __shared__ __half hsm[];
    __half* Ct = hsm;
    __half* Bt = hsm + 128*136;
    uint32_t ctSm = smem_u32(Ct), btSm = smem_u32(Bt);

    int bc = blockIdx.z;
    int b = bc / NCHK, c = bc % NCHK;
    int lt = blockIdx.x*128, st = blockIdx.y*128;
    int rowbase = b*LL + c*CHUNKSZ;
    int t = threadIdx.x, lane = t & 31, warp = t >> 5;
    int wl = warp & 1, wn = warp >> 1;
    int gid = lane >> 2, tg = lane & 3;
    int lr = lane & 7, lsm = lane >> 3;

    #pragma unroll 4
    for (int i=0;i<32;i++){
        int f = i*256 + t; int r = f >> 6, cp = (f & 63)*2;
        float2 cv = *(const float2*)(xbc + (size_t)(rowbase+lt+r)*CONVDIM + 2176 + cp);
        float2 bv = *(const float2*)(xbc + (size_t)(rowbase+st+r)*CONVDIM + 2048 + cp);
        *(__half2*)&Ct[r*136+cp] = __floats2half2_rn(cv.x, cv.y);
        *(__half2*)&Bt[r*136+cp] = __floats2half2_rn(bv.x, bv.y);
    }
    __syncthreads();

    float acc[4][4][4] = {};
    #pragma unroll
    for (int kk=0; kk<8; kk++){
        int kc = kk*16;
        uint32_t af[4][4], bf[4][2];
        #pragma unroll
        for (int mt=0;mt<4;mt++){
            uint32_t addr = ctSm + (uint32_t)((wl*64+mt*16 + (lsm&1)*8 + lr)*136 + kc + (lsm>>1)*8)*2;
            LDSM4(af[mt][0], af[mt][1], af[mt][2], af[mt][3], addr);
        }
        #pragma unroll
        for (int g=0;g<2;g++){
            uint32_t addr = btSm + (uint32_t)((wn*32+g*16 + (lsm&1)*8 + lr)*136 + kc + (lsm>>1)*8)*2;
            uint32_t r0,r1,r2,r3;
            LDSM4(r0,r1,r2,r3, addr);
            bf[2*g][0]=r0; bf[2*g+1][0]=r1; bf[2*g][1]=r2; bf[2*g+1][1]=r3;
        }
        #pragma unroll
        for (int mt=0;mt<4;mt++)
            #pragma unroll
            for (int nt=0;nt<4;nt++)
                MMA_F16(acc[mt][nt], af[mt], bf[nt]);
    }

    #pragma unroll
    for (int mt=0;mt<4;mt++){
        int l0 = lt + wl*64 + mt*16 + gid;
        #pragma unroll
        for (int nt=0;nt<4;nt++){
            int s0 = st + wn*32 + nt*8 + tg*2;
            *(__half2*)(Gh + ((size_t)bc*CHUNKSZ + l0)*CHUNKSZ + s0) =
                __floats2half2_rn(acc[mt][nt][0], acc[mt][nt][1]);
            *(__half2*)(Gh + ((size_t)bc*CHUNKSZ + l0 + 8)*CHUNKSZ + s0) =
                __floats2half2_rn(acc[mt][nt][2], acc[mt][nt][3]);
        }
    }
}

// ---------------- K7: Y_diag fp16 MMA per (b,c,h), exp-chain fill ----------------
#define YD_SMEM (256*72*2 + 64*72*2 + 256*4 + 256*4 + 64*4)
__global__ __launch_bounds__(256) void ydiag_h_kernel(const float* __restrict__ xbc,
                                                      const float* __restrict__ dtv,
                                                      const float* __restrict__ Acum,
                                                      const __half* __restrict__ Gh,
                                                      float* __restrict__ ydiag){
    extern __shared__ __half hsm[];
    __half* Mh = hsm;                 // [256 l][72]
    __half* Xh = hsm + 256*72;        // [64 s][72] (cols = p)
    float* aL  = (float*)(hsm + 256*72 + 64*72);
    float* r4  = aL + 256;            // r4[r] = exp(aL[r]-aL[r-4])
    float* dts = r4 + 256;
    uint32_t mSm = smem_u32(Mh), xSm = smem_u32(Xh);

    int bid = blockIdx.x;
    int h = bid % NH; int c = (bid/NH) % NCHK; int b = bid/(NH*NCHK);
    int bc = b*NCHK + c;
    int rowbase = b*LL + c*CHUNKSZ;
    int t = threadIdx.x, lane = t & 31, warp = t >> 5;
    int wl = warp >> 1, wp = warp & 1;     // 4(l) x 2(p)
    int gid = lane >> 2, tg = lane & 3;
    int lr = lane & 7, lsm = lane >> 3;
    const __half* Gb = Gh + (size_t)bc*CHUNKSZ*CHUNKSZ;

    aL[t] = Acum[(size_t)bid*CHUNKSZ + t];
    __syncthreads();
    r4[t] = (t >= 4) ? __expf(aL[t] - aL[t-4]) : 1.f;

    float acc[4][4][4] = {};
    int colf = t & 63;          // fixed column within sb tile
    int phase = t >> 6;         // row phase 0..3

    for (int sb=0; sb<4; sb++){
        int s0 = sb*64;
        __syncthreads();
        if (t < 64) dts[t] = dtv[(size_t)(rowbase+s0+t)*NH + h];
        __syncthreads();
        // build M tile [256 l][64 s] = tril(G)·exp(aL[l]-aL[s]) via per-thread exp chain
        {
            int sg = s0 + colf;
            float e = -1.f;
            #pragma unroll 8
            for (int i=0;i<64;i++){
                int row = i*4 + phase;
                float val = 0.f;
                if (row >= sg){
                    if (e < 0.f) e = __expf(aL[row] - aL[sg]);
                    else         e *= r4[row];
                    val = __half2float(Gb[(size_t)row*CHUNKSZ + sg]) * e;
                }
                Mh[row*72+colf] = __float2half_rn(val);
            }
        }
        // build Xd tile [64 s][64 p] = x * dt
        #pragma unroll 4
        for (int i=0;i<16;i++){
            int f = i*256 + t; int row = f >> 6, col = f & 63;
            float xv = xbc[(size_t)(rowbase+s0+row)*CONVDIM + h*HD + col];
            Xh[row*72+col] = __float2half_rn(xv * dts[row]);
        }
        __syncthreads();
        if (sb <= wl){
            #pragma unroll
            for (int kk=0; kk<4; kk++){
                int kc = kk*16;
                uint32_t af[4][4], bf[4][2];
                #pragma unroll
                for (int mt=0;mt<4;mt++){
                    uint32_t addr = mSm + (uint32_t)((wl*64+mt*16 + (lsm&1)*8 + lr)*72 + kc + (lsm>>1)*8)*2;
                    LDSM4(af[mt][0], af[mt][1], af[mt][2], af[mt][3], addr);
                }
                #pragma unroll
                for (int g=0;g<2;g++){
                    uint32_t addr = xSm + (uint32_t)((kc + (lsm&1)*8 + lr)*72 + wp*32 + g*16 + (lsm>>1)*8)*2;
                    uint32_t r0,r1,r2,r3;
                    LDSM4T(r0,r1,r2,r3, addr);
                    bf[2*g][0]=r0; bf[2*g][1]=r1; bf[2*g+1][0]=r2; bf[2*g+1][1]=r3;
                }
                #pragma unroll
                for (int mt=0;mt<4;mt++)
                    #pragma unroll
                    for (int nt=0;nt<4;nt++)
                        MMA_F16(acc[mt][nt], af[mt], bf[nt]);
            }
        }
    }

    #pragma unroll
    for (int mt=0;mt<4;mt++){
        int l0 = wl*64 + mt*16 + gid;
        #pragma unroll
        for (int nt=0;nt<4;nt++){
            int p0 = wp*32 + nt*8 + tg*2;
            *(float2*)(ydiag + (size_t)(rowbase+l0)*DIN + h*HD + p0) =
                make_float2(acc[mt][nt][0], acc[mt][nt][1]);
            *(float2*)(ydiag + (size_t)(rowbase+l0+8)*DIN + h*HD + p0) =
                make_float2(acc[mt][nt][2], acc[mt][nt][3]);
        }
    }
}

// ---------------- K8: states fp16 MMA per (b,c,h): S[p,n] ----------------
#define ST_SMEM (128*72*2 + 128*136*2 + 128*4)
__global__ __launch_bounds__(256) void states_h_kernel(const float* __restrict__ xbc,
                                                       const float* __restrict__ dtv,
                                                       const float* __restrict__ Acum,
                                                       float* __restrict__ states){
    extern __shared__ __half hsm[];
    __half* Xc = hsm;
    __half* Bt = hsm + 128*72;
    float* cl = (float*)(hsm + 128*72 + 128*136);
    uint32_t xSm = smem_u32(Xc), bSm = smem_u32(Bt);

    int bid = blockIdx.x;
    int h = bid % NH; int c = (bid/NH) % NCHK; int b = bid/(NH*NCHK);
    int rowbase = b*LL + c*CHUNKSZ;
    int t = threadIdx.x, lane = t & 31, warp = t >> 5;
    int wm = warp & 1, wn = warp >> 1;
    int gid = lane >> 2, tg = lane & 3;
    int lr = lane & 7, lsm = lane >> 3;

    float Atot = Acum[(size_t)bid*CHUNKSZ + 255];
    float acc[2][4][4] = {};

    for (int ch=0; ch<2; ch++){
        int l0 = ch*128;
        __syncthreads();
        if (t < 128){
            int l = l0 + t;
            cl[t] = dtv[(size_t)(rowbase+l)*NH + h] * __expf(Atot - Acum[(size_t)bid*CHUNKSZ + l]);
        }
        __syncthreads();
        #pragma unroll 4
        for (int i=0;i<32;i++){
            int f = i*256 + t; int row = f >> 6, col = f & 63;
            float xv = xbc[(size_t)(rowbase+l0+row)*CONVDIM + h*HD + col];
            Xc[row*72+col] = __float2half_rn(xv * cl[row]);
        }
        #pragma unroll 4
        for (int i=0;i<32;i++){
            int f = i*256 + t; int row = f >> 6, cp = (f & 63)*2;
            float2 bv = *(const float2*)(xbc + (size_t)(rowbase+l0+row)*CONVDIM + 2048 + cp);
            *(__half2*)&Bt[row*136+cp] = __floats2half2_rn(bv.x, bv.y);
        }
        __syncthreads();
        #pragma unroll
        for (int kk=0; kk<8; kk++){
            int kc = kk*16;
            uint32_t af[2][4], bf[4][2];
            #pragma unroll
            for (int mt=0;mt<2;mt++){
                uint32_t addr = xSm + (uint32_t)((kc + (lsm&1)*8 + lr)*72 + wm*32 + mt*16 + (lsm>>1)*8)*2;
                uint32_t r0,r1,r2,r3;
                LDSM4T(r0,r1,r2,r3, addr);
                af[mt][0]=r0; af[mt][1]=r2; af[mt][2]=r1; af[mt][3]=r3;
            }
            #pragma unroll
            for (int g=0;g<2;g++){
                uint32_t addr = bSm + (uint32_t)((kc + (lsm&1)*8 + lr)*136 + wn*32 + g*16 + (lsm>>1)*8)*2;
                uint32_t r0,r1,r2,r3;
                LDSM4T(r0,r1,r2,r3, addr);
                bf[2*g][0]=r0; bf[2*g][1]=r1; bf[2*g+1][0]=r2; bf[2*g+1][1]=r3;
            }
            #pragma unroll
            for (int mt=0;mt<2;mt++)
                #pragma unroll
                for (int nt=0;nt<4;nt++)
                    MMA_F16(acc[mt][nt], af[mt], bf[nt]);
        }
    }

    #pragma unroll
    for (int mt=0;mt<2;mt++){
        int p0 = wm*32 + mt*16 + gid;
        #pragma unroll
        for (int nt=0;nt<4;nt++){
            int n0 = wn*32 + nt*8 + tg*2;
            *(float2*)(states + ((size_t)bid*HD + p0)*DS + n0) =
                make_float2(acc[mt][nt][0], acc[mt][nt][1]);
            *(float2*)(states + ((size_t)bid*HD + p0 + 8)*DS + n0) =
                make_float2(acc[mt][nt][2], acc[mt][nt][3]);
        }
    }
}

// ---------------- K9: inter-chunk scan ----------------
__global__ void scan_kernel(const float* __restrict__ states, const float* __restrict__ Acum,
                            float* __restrict__ prevS){
    int idx = blockIdx.x*blockDim.x + threadIdx.x;
    if (idx >= BB*NH*HD*DS) return;
    int n = idx & 127;
    int p = (idx >> 7) & 63;
    int h = (idx >> 13) & 31;
    int b = idx >> 18;
    float S = 0.f;
    for (int c=0;c<NCHK;c++){
        int bid = (b*NCHK + c)*NH + h;
        size_t off = ((size_t)bid*HD + p)*DS + n;
        prevS[off] = S;
        float T = Acum[(size_t)bid*CHUNKSZ + 255];
        S = expf(T)*S + states[off];
    }
}

// ---------------- K10: Y_off fp16 MMA + combine (in place into ydiag) ----------
#define YO_SMEM (256*136*2 + 64*136*2 + 256*4)
__global__ __launch_bounds__(256) void yoff_h_kernel(const float* __restrict__ xbc,
                                                     const float* __restrict__ Acum,
                                                     const float* __restrict__ prevS,
                                                     const float* __restrict__ Dskip,
                                                     float* __restrict__ y){
    extern __shared__ __half hsm[];
    __half* Ct = hsm;
    __half* St = hsm + 256*136;
    float* eL = (float*)(hsm + 256*136 + 64*136);
    uint32_t cSm = smem_u32(Ct), sSm = smem_u32(St);

    int bid = blockIdx.x;
    int h = bid % NH; int c = (bid/NH) % NCHK; int b = bid/(NH*NCHK);
    int rowbase = b*LL + c*CHUNKSZ;
    int t = threadIdx.x, lane = t & 31, warp = t >> 5;
    int wl = warp >> 1, wp = warp & 1;
    int gid = lane >> 2, tg = lane & 3;
    int lr = lane & 7, lsm = lane >> 3;
    const float* Sb = prevS + (size_t)bid*HD*DS;

    eL[t] = __expf(Acum[(size_t)bid*CHUNKSZ + t]);
    #pragma unroll 4
    for (int i=0;i<64;i++){
        int f = i*256 + t; int row = f >> 6, cp = (f & 63)*2;
        float2 cv = *(const float2*)(xbc + (size_t)(rowbase+row)*CONVDIM + 2176 + cp);
        *(__half2*)&Ct[row*136+cp] = __floats2half2_rn(cv.x, cv.y);
    }
    #pragma unroll 4
    for (int i=0;i<16;i++){
        int f = i*256 + t; int row = f >> 6, cp = (f & 63)*2;
        float2 sv = *(const float2*)(Sb + (size_t)row*DS + cp);
        *(__half2*)&St[row*136+cp] = __floats2half2_rn(sv.x, sv.y);
    }
    __syncthreads();

    float acc[4][4][4] = {};
    #pragma unroll
    for (int kk=0; kk<8; kk++){
        int kc = kk*16;
        uint32_t af[4][4], bf[4][2];
        #pragma unroll
        for (int mt=0;mt<4;mt++){
            uint32_t addr = cSm + (uint32_t)((wl*64+mt*16 + (lsm&1)*8 + lr)*136 + kc + (lsm>>1)*8)*2;
            LDSM4(af[mt][0], af[mt][1], af[mt][2], af[mt][3], addr);
        }
        #pragma unroll
        for (int g=0;g<2;g++){
            uint32_t addr = sSm + (uint32_t)((wp*32+g*16 + (lsm&1)*8 + lr)*136 + kc + (lsm>>1)*8)*2;
            uint32_t r0,r1,r2,r3;
            LDSM4(r0,r1,r2,r3, addr);
            bf[2*g][0]=r0; bf[2*g+1][0]=r1; bf[2*g][1]=r2; bf[2*g+1][1]=r3;
        }
        #pragma unroll
        for (int mt=0;mt<4;mt++)
            #pragma unroll
            for (int nt=0;nt<4;nt++)
                MMA_F16(acc[mt][nt], af[mt], bf[nt]);
    }

    float dsk = Dskip[h];
    #pragma unroll
    for (int mt=0;mt<4;mt++){
        int l0 = wl*64 + mt*16 + gid;
        float e0 = eL[l0], e1 = eL[l0+8];
        #pragma unroll
        for (int nt=0;nt<4;nt++){
            int p0 = wp*32 + nt*8 + tg*2;
            float* yo0 = y + (size_t)(rowbase+l0)*DIN + h*HD + p0;
            float* yo1 = y + (size_t)(rowbase+l0+8)*DIN + h*HD + p0;
            float2 yd0 = *(float2*)yo0, yd1 = *(float2*)yo1;
            float2 x0 = *(const float2*)(xbc + (size_t)(rowbase+l0)*CONVDIM + h*HD + p0);
            float2 x1 = *(const float2*)(xbc + (size_t)(rowbase+l0+8)*CONVDIM + h*HD + p0);
            yd0.x += e0*acc[mt][nt][0] + x0.x*dsk;
            yd0.y += e0*acc[mt][nt][1] + x0.y*dsk;
            yd1.x += e1*acc[mt][nt][2] + x1.x*dsk;
            yd1.y += e1*acc[mt][nt][3] + x1.y*dsk;
            *(float2*)yo0 = yd0;
            *(float2*)yo1 = yd1;
        }
    }
}

// ---------------- K11: gated RMSNorm over D_INNER=2048 (half output) ----------------
__global__ __launch_bounds__(256) void gatenorm_kernel(const float* __restrict__ y,
                                                       const float* __restrict__ zx,
                                                       const float* __restrict__ gw,
                                                       __half* __restrict__ out){
    int row = blockIdx.x, t = threadIdx.x;
    const float* yr = y + (size_t)row*DIN;
    const float* zr = zx + (size_t)row*DPROJ;
    float vals[8]; float ss = 0.f;
    #pragma unroll
    for (int i=0;i<2;i++){
        int cbase = (i*256 + t)*4;
        float4 yv = *(const float4*)(yr + cbase);
        float4 zv = *(const float4*)(zr + cbase);
        float a;
        a = yv.x * siluf(zv.x); vals[i*4+0] = a; ss += a*a;
        a = yv.y * siluf(zv.y); vals[i*4+1] = a; ss += a*a;
        a = yv.z * siluf(zv.z); vals[i*4+2] = a; ss += a*a;
        a = yv.w * siluf(zv.w); vals[i*4+3] = a; ss += a*a;
    }
    __shared__ float red[8];
    for (int o=16;o>0;o>>=1) ss += __shfl_down_sync(0xffffffffu, ss, o);
    if ((t&31)==0) red[t>>5] = ss;
    __syncthreads();
    if (t < 32){
        float s2 = (t<8)? red[t] : 0.f;
        for (int o=4;o>0;o>>=1) s2 += __shfl_down_sync(0xffffffffu, s2, o);
        if (t==0) red[0] = s2;
    }
    __syncthreads();
    float scale = rsqrtf(red[0]/(float)DIN + EPSV);
    #pragma unroll
    for (int i=0;i<2;i++){
        int cbase = (i*256 + t)*4;
        float4 wv = *(const float4*)(gw + cbase);
        __half2 hs[2];
        hs[0] = __floats2half2_rn(vals[i*4+0]*scale*wv.x, vals[i*4+1]*scale*wv.y);
        hs[1] = __floats2half2_rn(vals[i*4+2]*scale*wv.z, vals[i*4+3]*scale*wv.w);
        *(uint2*)(out + (size_t)row*DIN + cbase) = *(uint2*)hs;
    }
}

// ---------------- launch ----------------
extern "C" void kernel_launch(void* const* d_in, const int* in_sizes, int n_in,
                              void* d_out, int out_size){
    const float* hidden  = (const float*)d_in[0];
    const float* norm_w  = (const float*)d_in[1];
    const float* in_proj = (const float*)d_in[2];
    const float* conv_w  = (const float*)d_in[3];
    const float* conv_b  = (const float*)d_in[4];
    const float* dt_bias = (const float*)d_in[5];
    const float* A_log   = (const float*)d_in[6];
    const float* Dsk     = (const float*)d_in[7];
    const float* gnw     = (const float*)d_in[8];
    const float* out_w   = (const float*)d_in[9];
    float* out = (float*)d_out;

    float *p_zx, *p_xbc, *p_dtv, *p_acum, *p_states, *p_prevS, *p_ydiag;
    __half *p_xh, *p_ygh, *p_wAh, *p_wBh, *p_gh;
    cudaGetSymbolAddress((void**)&p_xh,    g_xh);
    cudaGetSymbolAddress((void**)&p_zx,    g_zxbcdt);
    cudaGetSymbolAddress((void**)&p_xbc,   g_xBCc);
    cudaGetSymbolAddress((void**)&p_dtv,   g_dtv);
    cudaGetSymbolAddress((void**)&p_acum,  g_Acum);
    cudaGetSymbolAddress((void**)&p_gh,    g_Gh);
    cudaGetSymbolAddress((void**)&p_states,g_states);
    cudaGetSymbolAddress((void**)&p_prevS, g_prevS);
    cudaGetSymbolAddress((void**)&p_ydiag, g_ydiag);
    cudaGetSymbolAddress((void**)&p_ygh,   g_ygh);
    cudaGetSymbolAddress((void**)&p_wAh,   g_wAh);
    cudaGetSymbolAddress((void**)&p_wBh,   g_wBh);

    cudaFuncSetAttribute(h16gemm_kernel, cudaFuncAttributeMaxDynamicSharedMemorySize, GEMM_SMEM);
    cudaFuncSetAttribute(gmat_h_kernel,  cudaFuncAttributeMaxDynamicSharedMemorySize, GM_SMEM);
    cudaFuncSetAttribute(ydiag_h_kernel, cudaFuncAttributeMaxDynamicSharedMemorySize, YD_SMEM);
    cudaFuncSetAttribute(states_h_kernel,cudaFuncAttributeMaxDynamicSharedMemorySize, ST_SMEM);
    cudaFuncSetAttribute(yoff_h_kernel,  cudaFuncAttributeMaxDynamicSharedMemorySize, YO_SMEM);

    // 0. convert weights to half
    f2h_kernel<<<(DM*DPROJ/4 + 255)/256, 256>>>(in_proj, p_wAh, DM*DPROJ/4);
    f2h_kernel<<<(DIN*DM/4 + 255)/256, 256>>>(out_w, p_wBh, DIN*DM/4);
    // 1. RMSNorm (emits half)
    rmsnorm_kernel<<<NTOK, 256>>>(hidden, norm_w, p_xh);
    // 2. in_proj GEMM (fp16 tensor cores)
    h16gemm_kernel<<<dim3((DPROJ+127)/128, NTOK/128), 256, GEMM_SMEM>>>(NTOK, DPROJ, DM, p_xh, p_wAh, nullptr, p_zx);
    // 3. conv1d + bias + silu
    conv_kernel<<<(NTOK*CONVDIM + 255)/256, 256>>>(p_zx, conv_w, conv_b, p_xbc);
    // 4. dt softplus
    dt_kernel<<<(NTOK*NH + 255)/256, 256>>>(p_zx, dt_bias, p_dtv);
    // 5. per-chunk cumsum
    cumsum_kernel<<<BB*NCHK*NH, 256>>>(p_dtv, A_log, p_acum);
    // 6. G = C·B^T (fp16 MMA, half output)
    gmat_h_kernel<<<dim3(2,2,BB*NCHK), 256, GM_SMEM>>>(p_xbc, p_gh);
    // 7. Y_diag (fp16 MMA, exp-chain)
    ydiag_h_kernel<<<BB*NCHK*NH, 256, YD_SMEM>>>(p_xbc, p_dtv, p_acum, p_gh, p_ydiag);
    // 8. chunk states (fp16 MMA)
    states_h_kernel<<<BB*NCHK*NH, 256, ST_SMEM>>>(p_xbc, p_dtv, p_acum, p_states);
    // 9. inter-chunk scan
    scan_kernel<<<(BB*NH*HD*DS + 255)/256, 256>>>(p_states, p_acum, p_prevS);
    // 10. Y_off (fp16 MMA) + combine + D skip
    yoff_h_kernel<<<BB*NCHK*NH, 256, YO_SMEM>>>(p_xbc, p_acum, p_prevS, Dsk, p_ydiag);
    // 11. gated RMSNorm (emits half)
    gatenorm_kernel<<<NTOK, 256>>>(p_ydiag, p_zx, gnw, p_ygh);
    // 12. out_proj GEMM (fp16) + residual
    h16gemm_kernel<<<dim3(DM/128, NTOK/128), 256, GEMM_SMEM>>>(NTOK, DM, DIN, p_ygh, p_wBh, hidden, out);
}

// round 13
// speedup vs baseline: 1.1314x; 1.1314x over previous
#include <cuda_runtime.h>
#include <cuda_fp16.h>
#include <math.h>
#include <stdint.h>

// ---------------- problem constants ----------------
#define BB 2
#define LL 4096
#define DM 1024
#define DIN 2048
#define NH 32
#define HD 64
#define DS 128
#define CHUNKSZ 256
#define NCHK 16
#define CONVDIM 2304        // DIN + 2*DS
#define DPROJ 4384          // 2*DIN + 2*DS + NH
#define NTOK (BB*LL)        // 8192
#define EPSV 1e-5f

// ---------------- scratch (device globals; no allocs allowed) ----------------
__device__ __half g_xh[(size_t)NTOK*DM];                // rmsnorm output (half)
__device__ float g_zxbcdt[(size_t)NTOK*DPROJ];
__device__ __half g_xBCh[(size_t)NTOK*CONVDIM];         // conv output (half)
__device__ float g_dtv[(size_t)NTOK*NH];
__device__ float g_Acum[(size_t)BB*NCHK*NH*CHUNKSZ];
__device__ __half g_Gh[(size_t)BB*NCHK*CHUNKSZ*CHUNKSZ];  // G in half
__device__ float g_states[(size_t)BB*NCHK*NH*HD*DS];
__device__ float g_prevS[(size_t)BB*NCHK*NH*HD*DS];
__device__ float g_ydiag[(size_t)NTOK*DIN];             // also final y (in place)
__device__ __half g_ygh[(size_t)NTOK*DIN];              // gatenorm output (half)
__device__ __half g_wAh[(size_t)DM*DPROJ];              // half in_proj_w
__device__ __half g_wBh[(size_t)DIN*DM];                // half out_proj_w

__device__ __forceinline__ float siluf(float x){ return x / (1.f + __expf(-x)); }

__device__ __forceinline__ uint32_t smem_u32(const void* p){
    uint32_t a;
    asm("{ .reg .u64 t; cvta.to.shared.u64 t, %1; cvt.u32.u64 %0, t; }" : "=r"(a) : "l"(p));
    return a;
}

__device__ __forceinline__ void cpa16(uint32_t dst, const void* src, bool pred){
    int sz = pred ? 16 : 0;
    asm volatile("cp.async.cg.shared.global [%0], [%1], 16, %2;" :: "r"(dst), "l"(src), "r"(sz));
}

#define CP_COMMIT() asm volatile("cp.async.commit_group;")
#define CP_WAIT2()  asm volatile("cp.async.wait_group 2;")

#define LDSM4(r0,r1,r2,r3,addr) \
    asm volatile("ldmatrix.sync.aligned.m8n8.x4.shared.b16 {%0,%1,%2,%3}, [%4];" \
        : "=r"(r0),"=r"(r1),"=r"(r2),"=r"(r3) : "r"(addr))

#define LDSM4T(r0,r1,r2,r3,addr) \
    asm volatile("ldmatrix.sync.aligned.m8n8.x4.trans.shared.b16 {%0,%1,%2,%3}, [%4];" \
        : "=r"(r0),"=r"(r1),"=r"(r2),"=r"(r3) : "r"(addr))

#define MMA_F16(c, a, b) \
    asm volatile("mma.sync.aligned.m16n8k16.row.col.f32.f16.f16.f32 " \
        "{%0,%1,%2,%3}, {%4,%5,%6,%7}, {%8,%9}, {%0,%1,%2,%3};" \
        : "+f"((c)[0]),"+f"((c)[1]),"+f"((c)[2]),"+f"((c)[3]) \
        : "r"((a)[0]),"r"((a)[1]),"r"((a)[2]),"r"((a)[3]), "r"((b)[0]),"r"((b)[1]))

// ---------------- K0: convert fp32 array to half ----------------
__global__ void f2h_kernel(const float* __restrict__ in, __half* __restrict__ out, int n4){
    int i = blockIdx.x*blockDim.x + threadIdx.x;
    if (i >= n4) return;
    float4 v = ((const float4*)in)[i];
    __half2 hs[2];
    hs[0] = __floats2half2_rn(v.x, v.y);
    hs[1] = __floats2half2_rn(v.z, v.w);
    *(uint2*)(out + (size_t)i*4) = *(uint2*)hs;
}

// ---------------- K1: RMSNorm over D_MODEL=1024 (half output) ----------------
__global__ __launch_bounds__(256) void rmsnorm_kernel(const float* __restrict__ x,
                                                      const float* __restrict__ w,
                                                      __half* __restrict__ out){
    int row = blockIdx.x;
    int t = threadIdx.x;
    float4 v = ((const float4*)(x + (size_t)row*DM))[t];
    float ss = v.x*v.x + v.y*v.y + v.z*v.z + v.w*v.w;
    __shared__ float red[8];
    for (int o=16;o>0;o>>=1) ss += __shfl_down_sync(0xffffffffu, ss, o);
    if ((t&31)==0) red[t>>5] = ss;
    __syncthreads();
    if (t < 32){
        float s2 = (t<8)? red[t] : 0.f;
        for (int o=4;o>0;o>>=1) s2 += __shfl_down_sync(0xffffffffu, s2, o);
        if (t==0) red[0] = s2;
    }
    __syncthreads();
    float scale = rsqrtf(red[0]/(float)DM + EPSV);
    float4 wv = ((const float4*)w)[t];
    __half2 hs[2];
    hs[0] = __floats2half2_rn(v.x*scale*wv.x, v.y*scale*wv.y);
    hs[1] = __floats2half2_rn(v.z*scale*wv.z, v.w*scale*wv.w);
    *(uint2*)(out + (size_t)row*DM + t*4) = *(uint2*)hs;
}

// ---------------- FP16 GEMM: 128x128 block, BK=32, 4-stage cp.async, 2 CTAs/SM ----
#define AH_STRIDE 40
#define BH_STRIDE 136
#define ASTG_H (128*AH_STRIDE)
#define BSTG_H (32*BH_STRIDE)
#define NSTAGE 4
#define GEMM_SMEM ((NSTAGE*(ASTG_H + BSTG_H))*2)

__global__ __launch_bounds__(256, 2) void h16gemm_kernel(int M, int N, int K,
                                                         const __half* __restrict__ A,
                                                         const __half* __restrict__ B,
                                                         const float* __restrict__ Cadd,
                                                         float* __restrict__ C){
    extern __shared__ __half hsmem[];
    __half* As = hsmem;
    __half* Bs = hsmem + NSTAGE*ASTG_H;
    uint32_t aSm = smem_u32(As);
    uint32_t bSm = smem_u32(Bs);

    int tid = threadIdx.x, lane = tid & 31, warp = tid >> 5;
    int warpM = warp & 1, warpN = warp >> 1;
    int gid = lane >> 2, tg = lane & 3;
    int lr = lane & 7, ls = lane >> 3;
    int rowBlk = blockIdx.y*128, colBase = blockIdx.x*128;

    int aRow = tid >> 1, aKc = (tid & 1)*16;
    int bK = tid >> 3, bN = (tid & 7)*16;

    const __half* Ag = A + (size_t)(rowBlk + aRow)*K + aKc;
    const __half* Bg = B + (size_t)bK*N + colBase + bN;
    bool p0 = (colBase + bN) < N;
    bool p1 = (colBase + bN + 8) < N;

    float acc[4][4][4] = {};
    int KT = K >> 5;

    #pragma unroll
    for (int s=0; s<3; s++){
        uint32_t ad = aSm + (uint32_t)(s*ASTG_H + aRow*AH_STRIDE + aKc)*2;
        const __half* ap = Ag + s*32;
        cpa16(ad, ap, true);
        cpa16(ad+16, ap+8, true);
        uint32_t bd = bSm + (uint32_t)(s*BSTG_H + bK*BH_STRIDE + bN)*2;
        const __half* bpp = Bg + (size_t)s*32*N;
        cpa16(bd, p0 ? bpp : B, p0);
        cpa16(bd+16, p1 ? bpp+8 : B, p1);
        CP_COMMIT();
    }

    for (int kt=0; kt<KT; kt++){
        int s = kt % NSTAGE;
        CP_WAIT2();
        __syncthreads();
        if (kt+3 < KT){
            int s2 = (kt+3) % NSTAGE;
            uint32_t ad = aSm + (uint32_t)(s2*ASTG_H + aRow*AH_STRIDE + aKc)*2;
            const __half* ap = Ag + (kt+3)*32;
            cpa16(ad, ap, true);
            cpa16(ad+16, ap+8, true);
            uint32_t bd = bSm + (uint32_t)(s2*BSTG_H + bK*BH_STRIDE + bN)*2;
            const __half* bpp = Bg + (size_t)(kt+3)*32*N;
            cpa16(bd, p0 ? bpp : B, p0);
            cpa16(bd+16, p1 ? bpp+8 : B, p1);
        }
        CP_COMMIT();

        uint32_t aBase = aSm + (uint32_t)(s*ASTG_H)*2;
        uint32_t bBase = bSm + (uint32_t)(s*BSTG_H)*2;
        #pragma unroll
        for (int kk=0; kk<2; kk++){
            int kc = kk*16;
            uint32_t af[4][4], bf[4][2];
            #pragma unroll
            for (int mt=0;mt<4;mt++){
                int m0 = warpM*64 + mt*16;
                uint32_t addr = aBase + (uint32_t)((m0 + (ls&1)*8 + lr)*AH_STRIDE + kc + (ls>>1)*8)*2;
                LDSM4(af[mt][0], af[mt][1], af[mt][2], af[mt][3], addr);
            }
            #pragma unroll
            for (int ntp=0;ntp<2;ntp++){
                int n0 = warpN*32 + ntp*16;
                uint32_t addr = bBase + (uint32_t)((kc + (ls&1)*8 + lr)*BH_STRIDE + n0 + (ls>>1)*8)*2;
                uint32_t r0,r1,r2,r3;
                LDSM4T(r0,r1,r2,r3, addr);
                bf[2*ntp][0]=r0; bf[2*ntp][1]=r1;
                bf[2*ntp+1][0]=r2; bf[2*ntp+1][1]=r3;
            }
            #pragma unroll
            for (int mt=0;mt<4;mt++)
                #pragma unroll
                for (int nt=0;nt<4;nt++)
                    MMA_F16(acc[mt][nt], af[mt], bf[nt]);
        }
    }

    #pragma unroll
    for (int mt=0;mt<4;mt++){
        int row0 = rowBlk + warpM*64 + mt*16 + gid;
        #pragma unroll
        for (int nt=0;nt<4;nt++){
            int col = colBase + warpN*32 + nt*8 + tg*2;
            if (col < N){
                float2 v0 = make_float2(acc[mt][nt][0], acc[mt][nt][1]);
                float2 v1 = make_float2(acc[mt][nt][2], acc[mt][nt][3]);
                if (Cadd){
                    float2 r0 = *(const float2*)(Cadd + (size_t)row0*N + col);
                    float2 r1 = *(const float2*)(Cadd + (size_t)(row0+8)*N + col);
                    v0.x += r0.x; v0.y += r0.y;
                    v1.x += r1.x; v1.y += r1.y;
                }
                *(float2*)(C + (size_t)row0*N + col) = v0;
                *(float2*)(C + (size_t)(row0+8)*N + col) = v1;
            }
        }
    }
}

// ---------------- K3: causal depthwise conv1d (k=4) + bias + SiLU (half out) ------
__global__ void conv_kernel(const float* __restrict__ zx, const float* __restrict__ cw,
                            const float* __restrict__ cb, __half* __restrict__ out){
    int idx = blockIdx.x*blockDim.x + threadIdx.x;
    if (idx >= NTOK*CONVDIM/2) return;
    int cpair = idx % (CONVDIM/2);
    int row = idx / (CONVDIM/2);
    int c = cpair*2;
    int l = row & (LL-1);
    float a0 = cb[c], a1 = cb[c+1];
    #pragma unroll
    for (int k=0;k<4;k++){
        int ls = l - 3 + k;
        if (ls >= 0){
            float2 v = *(const float2*)(zx + (size_t)(row-3+k)*DPROJ + DIN + c);
            a0 += v.x * cw[c*4+k];
            a1 += v.y * cw[(c+1)*4+k];
        }
    }
    *(__half2*)(out + (size_t)row*CONVDIM + c) = __floats2half2_rn(siluf(a0), siluf(a1));
}

// ---------------- K4: dt = softplus(dt_raw + dt_bias) ----------------
__global__ void dt_kernel(const float* __restrict__ zx, const float* __restrict__ dt_bias,
                          float* __restrict__ dtv){
    int idx = blockIdx.x*blockDim.x + threadIdx.x;
    if (idx >= NTOK*NH) return;
    int h = idx & (NH-1);
    int row = idx / NH;
    float x = zx[(size_t)row*DPROJ + (DIN + CONVDIM) + h] + dt_bias[h];
    dtv[idx] = (x > 20.f) ? x : log1pf(expf(x));
}

// ---------------- K5: per-(b,c,h) inclusive cumsum of dt*A over chunk ----------------
__global__ __launch_bounds__(256) void cumsum_kernel(const float* __restrict__ dtv,
                                                     const float* __restrict__ A_log,
                                                     float* __restrict__ Acum){
    int bid = blockIdx.x;
    int h = bid % NH; int c = (bid/NH) % NCHK; int b = bid/(NH*NCHK);
    int t = threadIdx.x;
    int row = b*LL + c*CHUNKSZ + t;
    float negA = -expf(A_log[h]);
    float v = dtv[(size_t)row*NH + h] * negA;
    __shared__ float sh[256];
    sh[t] = v; __syncthreads();
    for (int off=1; off<256; off<<=1){
        float add = (t >= off) ? sh[t-off] : 0.f;
        __syncthreads();
        sh[t] += add;
        __syncthreads();
    }
    Acum[(size_t)bid*CHUNKSZ + t] = sh[t];
}

// ---------------- K6: gmat fp16 MMA: G = C·B^T per (b,c), half in/out ----------
#define GM_SMEM (2*128*136*2)
__global__ __launch_bounds__(256) void gmat_h_kernel(const __half* __restrict__ xbc,
                                                     __half* __restrict__ Gh){
    extern __shared__ __half hsm[];
    __half* Ct = hsm;
    __half* Bt = hsm + 128*136;
    uint32_t ctSm = smem_u32(Ct), btSm = smem_u32(Bt);

    int bc = blockIdx.z;
    int b = bc / NCHK, c = bc % NCHK;
    int lt = blockIdx.x*128, st = blockIdx.y*128;
    int rowbase = b*LL + c*CHUNKSZ;
    int t = threadIdx.x, lane = t & 31, warp = t >> 5;
    int wl = warp & 1, wn = warp >> 1;
    int gid = lane >> 2, tg = lane & 3;
    int lr = lane & 7, lsm = lane >> 3;

    #pragma unroll 4
    for (int i=0;i<32;i++){
        int f = i*256 + t; int r = f >> 6, cp = (f & 63)*2;
        *(__half2*)&Ct[r*136+cp] = *(const __half2*)(xbc + (size_t)(rowbase+lt+r)*CONVDIM + 2176 + cp);
        *(__half2*)&Bt[r*136+cp] = *(const __half2*)(xbc + (size_t)(rowbase+st+r)*CONVDIM + 2048 + cp);
    }
    __syncthreads();

    float acc[4][4][4] = {};
    #pragma unroll
    for (int kk=0; kk<8; kk++){
        int kc = kk*16;
        uint32_t af[4][4], bf[4][2];
        #pragma unroll
        for (int mt=0;mt<4;mt++){
            uint32_t addr = ctSm + (uint32_t)((wl*64+mt*16 + (lsm&1)*8 + lr)*136 + kc + (lsm>>1)*8)*2;
            LDSM4(af[mt][0], af[mt][1], af[mt][2], af[mt][3], addr);
        }
        #pragma unroll
        for (int g=0;g<2;g++){
            uint32_t addr = btSm + (uint32_t)((wn*32+g*16 + (lsm&1)*8 + lr)*136 + kc + (lsm>>1)*8)*2;
            uint32_t r0,r1,r2,r3;
            LDSM4(r0,r1,r2,r3, addr);
            bf[2*g][0]=r0; bf[2*g+1][0]=r1; bf[2*g][1]=r2; bf[2*g+1][1]=r3;
        }
        #pragma unroll
        for (int mt=0;mt<4;mt++)
            #pragma unroll
            for (int nt=0;nt<4;nt++)
                MMA_F16(acc[mt][nt], af[mt], bf[nt]);
    }

    #pragma unroll
    for (int mt=0;mt<4;mt++){
        int l0 = lt + wl*64 + mt*16 + gid;
        #pragma unroll
        for (int nt=0;nt<4;nt++){
            int s0 = st + wn*32 + nt*8 + tg*2;
            *(__half2*)(Gh + ((size_t)bc*CHUNKSZ + l0)*CHUNKSZ + s0) =
                __floats2half2_rn(acc[mt][nt][0], acc[mt][nt][1]);
            *(__half2*)(Gh + ((size_t)bc*CHUNKSZ + l0 + 8)*CHUNKSZ + s0) =
                __floats2half2_rn(acc[mt][nt][2], acc[mt][nt][3]);
        }
    }
}

// ---------------- K7: Y_diag fp16 MMA per (b,c,h) ----------------
#define YD_SMEM (256*72*2 + 64*72*2 + 256*4 + 64*4)
__global__ __launch_bounds__(256) void ydiag_h_kernel(const __half* __restrict__ xbc,
                                                      const float* __restrict__ dtv,
                                                      const float* __restrict__ Acum,
                                                      const __half* __restrict__ Gh,
                                                      float* __restrict__ ydiag){
    extern __shared__ __half hsm[];
    __half* Mh = hsm;                 // [256 l][72]
    __half* Xh = hsm + 256*72;        // [64 s][72] (cols = p)
    float* aL  = (float*)(hsm + 256*72 + 64*72);
    float* dts = aL + 256;
    uint32_t mSm = smem_u32(Mh), xSm = smem_u32(Xh);

    int bid = blockIdx.x;
    int h = bid % NH; int c = (bid/NH) % NCHK; int b = bid/(NH*NCHK);
    int bc = b*NCHK + c;
    int rowbase = b*LL + c*CHUNKSZ;
    int t = threadIdx.x, lane = t & 31, warp = t >> 5;
    int wl = warp >> 1, wp = warp & 1;     // 4(l) x 2(p)
    int gid = lane >> 2, tg = lane & 3;
    int lr = lane & 7, lsm = lane >> 3;
    const __half* Gb = Gh + (size_t)bc*CHUNKSZ*CHUNKSZ;

    aL[t] = Acum[(size_t)bid*CHUNKSZ + t];
    float acc[4][4][4] = {};

    for (int sb=0; sb<4; sb++){
        int s0 = sb*64;
        __syncthreads();
        if (t < 64) dts[t] = dtv[(size_t)(rowbase+s0+t)*NH + h];
        __syncthreads();
        // M tile [256 l][64 s] = tril(G)·exp(aL[l]-aL[s])
        #pragma unroll 4
        for (int i=0;i<64;i++){
            int f = i*256 + t; int row = f >> 6, col = f & 63;
            int sg = s0 + col;
            __half val = __float2half_rn(0.f);
            if (sg <= row){
                float gv = __half2float(Gb[(size_t)row*CHUNKSZ + sg]);
                val = __float2half_rn(gv * __expf(aL[row] - aL[sg]));
            }
            Mh[row*72+col] = val;
        }
        // Xd tile [64 s][64 p] = x * dt
        #pragma unroll 4
        for (int i=0;i<16;i++){
            int f = i*256 + t; int row = f >> 6, col = f & 63;
            float xv = __half2float(xbc[(size_t)(rowbase+s0+row)*CONVDIM + h*HD + col]);
            Xh[row*72+col] = __float2half_rn(xv * dts[row]);
        }
        __syncthreads();
        if (sb <= wl){
            #pragma unroll
            for (int kk=0; kk<4; kk++){
                int kc = kk*16;
                uint32_t af[4][4], bf[4][2];
                #pragma unroll
                for (int mt=0;mt<4;mt++){
                    uint32_t addr = mSm + (uint32_t)((wl*64+mt*16 + (lsm&1)*8 + lr)*72 + kc + (lsm>>1)*8)*2;
                    LDSM4(af[mt][0], af[mt][1], af[mt][2], af[mt][3], addr);
                }
                #pragma unroll
                for (int g=0;g<2;g++){
                    uint32_t addr = xSm + (uint32_t)((kc + (lsm&1)*8 + lr)*72 + wp*32 + g*16 + (lsm>>1)*8)*2;
                    uint32_t r0,r1,r2,r3;
                    LDSM4T(r0,r1,r2,r3, addr);
                    bf[2*g][0]=r0; bf[2*g][1]=r1; bf[2*g+1][0]=r2; bf[2*g+1][1]=r3;
                }
                #pragma unroll
                for (int mt=0;mt<4;mt++)
                    #pragma unroll
                    for (int nt=0;nt<4;nt++)
                        MMA_F16(acc[mt][nt], af[mt], bf[nt]);
            }
        }
    }

    #pragma unroll
    for (int mt=0;mt<4;mt++){
        int l0 = wl*64 + mt*16 + gid;
        #pragma unroll
        for (int nt=0;nt<4;nt++){
            int p0 = wp*32 + nt*8 + tg*2;
            *(float2*)(ydiag + (size_t)(rowbase+l0)*DIN + h*HD + p0) =
                make_float2(acc[mt][nt][0], acc[mt][nt][1]);
            *(float2*)(ydiag + (size_t)(rowbase+l0+8)*DIN + h*HD + p0) =
                make_float2(acc[mt][nt][2], acc[mt][nt][3]);
        }
    }
}

// ---------------- K8: states fp16 MMA per (b,c,h): S[p,n] ----------------
#define ST_SMEM (128*72*2 + 128*136*2 + 128*4)
__global__ __launch_bounds__(256) void states_h_kernel(const __half* __restrict__ xbc,
                                                       const float* __restrict__ dtv,
                                                       const float* __restrict__ Acum,
                                                       float* __restrict__ states){
    extern __shared__ __half hsm[];
    __half* Xc = hsm;
    __half* Bt = hsm + 128*72;
    float* cl = (float*)(hsm + 128*72 + 128*136);
    uint32_t xSm = smem_u32(Xc), bSm = smem_u32(Bt);

    int bid = blockIdx.x;
    int h = bid % NH; int c = (bid/NH) % NCHK; int b = bid/(NH*NCHK);
    int rowbase = b*LL + c*CHUNKSZ;
    int t = threadIdx.x, lane = t & 31, warp = t >> 5;
    int wm = warp & 1, wn = warp >> 1;
    int gid = lane >> 2, tg = lane & 3;
    int lr = lane & 7, lsm = lane >> 3;

    float Atot = Acum[(size_t)bid*CHUNKSZ + 255];
    float acc[2][4][4] = {};

    for (int ch=0; ch<2; ch++){
        int l0 = ch*128;
        __syncthreads();
        if (t < 128){
            int l = l0 + t;
            cl[t] = dtv[(size_t)(rowbase+l)*NH + h] * __expf(Atot - Acum[(size_t)bid*CHUNKSZ + l]);
        }
        __syncthreads();
        #pragma unroll 4
        for (int i=0;i<32;i++){
            int f = i*256 + t; int row = f >> 6, col = f & 63;
            float xv = __half2float(xbc[(size_t)(rowbase+l0+row)*CONVDIM + h*HD + col]);
            Xc[row*72+col] = __float2half_rn(xv * cl[row]);
        }
        #pragma unroll 4
        for (int i=0;i<32;i++){
            int f = i*256 + t; int row = f >> 6, cp = (f & 63)*2;
            *(__half2*)&Bt[row*136+cp] = *(const __half2*)(xbc + (size_t)(rowbase+l0+row)*CONVDIM + 2048 + cp);
        }
        __syncthreads();
        #pragma unroll
        for (int kk=0; kk<8; kk++){
            int kc = kk*16;
            uint32_t af[2][4], bf[4][2];
            #pragma unroll
            for (int mt=0;mt<2;mt++){
                uint32_t addr = xSm + (uint32_t)((kc + (lsm&1)*8 + lr)*72 + wm*32 + mt*16 + (lsm>>1)*8)*2;
                uint32_t r0,r1,r2,r3;
                LDSM4T(r0,r1,r2,r3, addr);
                af[mt][0]=r0; af[mt][1]=r2; af[mt][2]=r1; af[mt][3]=r3;
            }
            #pragma unroll
            for (int g=0;g<2;g++){
                uint32_t addr = bSm + (uint32_t)((kc + (lsm&1)*8 + lr)*136 + wn*32 + g*16 + (lsm>>1)*8)*2;
                uint32_t r0,r1,r2,r3;
                LDSM4T(r0,r1,r2,r3, addr);
                bf[2*g][0]=r0; bf[2*g][1]=r1; bf[2*g+1][0]=r2; bf[2*g+1][1]=r3;
            }
            #pragma unroll
            for (int mt=0;mt<2;mt++)
                #pragma unroll
                for (int nt=0;nt<4;nt++)
                    MMA_F16(acc[mt][nt], af[mt], bf[nt]);
        }
    }

    #pragma unroll
    for (int mt=0;mt<2;mt++){
        int p0 = wm*32 + mt*16 + gid;
        #pragma unroll
        for (int nt=0;nt<4;nt++){
            int n0 = wn*32 + nt*8 + tg*2;
            *(float2*)(states + ((size_t)bid*HD + p0)*DS + n0) =
                make_float2(acc[mt][nt][0], acc[mt][nt][1]);
            *(float2*)(states + ((size_t)bid*HD + p0 + 8)*DS + n0) =
                make_float2(acc[mt][nt][2], acc[mt][nt][3]);
        }
    }
}

// ---------------- K9: inter-chunk scan ----------------
__global__ void scan_kernel(const float* __restrict__ states, const float* __restrict__ Acum,
                            float* __restrict__ prevS){
    int idx = blockIdx.x*blockDim.x + threadIdx.x;
    if (idx >= BB*NH*HD*DS) return;
    int n = idx & 127;
    int p = (idx >> 7) & 63;
    int h = (idx >> 13) & 31;
    int b = idx >> 18;
    float S = 0.f;
    for (int c=0;c<NCHK;c++){
        int bid = (b*NCHK + c)*NH + h;
        size_t off = ((size_t)bid*HD + p)*DS + n;
        prevS[off] = S;
        float T = Acum[(size_t)bid*CHUNKSZ + 255];
        S = expf(T)*S + states[off];
    }
}

// ---------------- K10: Y_off fp16 MMA + combine (in place into ydiag) ----------
#define YO_SMEM (256*136*2 + 64*136*2 + 256*4)
__global__ __launch_bounds__(256) void yoff_h_kernel(const __half* __restrict__ xbc,
                                                     const float* __restrict__ Acum,
                                                     const float* __restrict__ prevS,
                                                     const float* __restrict__ Dskip,
                                                     float* __restrict__ y){
    extern __shared__ __half hsm[];
    __half* Ct = hsm;
    __half* St = hsm + 256*136;
    float* eL = (float*)(hsm + 256*136 + 64*136);
    uint32_t cSm = smem_u32(Ct), sSm = smem_u32(St);

    int bid = blockIdx.x;
    int h = bid % NH; int c = (bid/NH) % NCHK; int b = bid/(NH*NCHK);
    int rowbase = b*LL + c*CHUNKSZ;
    int t = threadIdx.x, lane = t & 31, warp = t >> 5;
    int wl = warp >> 1, wp = warp & 1;
    int gid = lane >> 2, tg = lane & 3;
    int lr = lane & 7, lsm = lane >> 3;
    const float* Sb = prevS + (size_t)bid*HD*DS;

    eL[t] = __expf(Acum[(size_t)bid*CHUNKSZ + t]);
    #pragma unroll 4
    for (int i=0;i<64;i++){
        int f = i*256 + t; int row = f >> 6, cp = (f & 63)*2;
        *(__half2*)&Ct[row*136+cp] = *(const __half2*)(xbc + (size_t)(rowbase+row)*CONVDIM + 2176 + cp);
    }
    #pragma unroll 4
    for (int i=0;i<16;i++){
        int f = i*256 + t; int row = f >> 6, cp = (f & 63)*2;
        float2 sv = *(const float2*)(Sb + (size_t)row*DS + cp);
        *(__half2*)&St[row*136+cp] = __floats2half2_rn(sv.x, sv.y);
    }
    __syncthreads();

    float acc[4][4][4] = {};
    #pragma unroll
    for (int kk=0; kk<8; kk++){
        int kc = kk*16;
        uint32_t af[4][4], bf[4][2];
        #pragma unroll
        for (int mt=0;mt<4;mt++){
            uint32_t addr = cSm + (uint32_t)((wl*64+mt*16 + (lsm&1)*8 + lr)*136 + kc + (lsm>>1)*8)*2;
            LDSM4(af[mt][0], af[mt][1], af[mt][2], af[mt][3], addr);
        }
        #pragma unroll
        for (int g=0;g<2;g++){
            uint32_t addr = sSm + (uint32_t)((wp*32+g*16 + (lsm&1)*8 + lr)*136 + kc + (lsm>>1)*8)*2;
            uint32_t r0,r1,r2,r3;
            LDSM4(r0,r1,r2,r3, addr);
            bf[2*g][0]=r0; bf[2*g+1][0]=r1; bf[2*g][1]=r2; bf[2*g+1][1]=r3;
        }
        #pragma unroll
        for (int mt=0;mt<4;mt++)
            #pragma unroll
            for (int nt=0;nt<4;nt++)
                MMA_F16(acc[mt][nt], af[mt], bf[nt]);
    }

    float dsk = Dskip[h];
    #pragma unroll
    for (int mt=0;mt<4;mt++){
        int l0 = wl*64 + mt*16 + gid;
        float e0 = eL[l0], e1 = eL[l0+8];
        #pragma unroll
        for (int nt=0;nt<4;nt++){
            int p0 = wp*32 + nt*8 + tg*2;
            float* yo0 = y + (size_t)(rowbase+l0)*DIN + h*HD + p0;
            float* yo1 = y + (size_t)(rowbase+l0+8)*DIN + h*HD + p0;
            float2 yd0 = *(float2*)yo0, yd1 = *(float2*)yo1;
            __half2 xh0 = *(const __half2*)(xbc + (size_t)(rowbase+l0)*CONVDIM + h*HD + p0);
            __half2 xh1 = *(const __half2*)(xbc + (size_t)(rowbase+l0+8)*CONVDIM + h*HD + p0);
            float2 x0 = __half22float2(xh0);
            float2 x1 = __half22float2(xh1);
            yd0.x += e0*acc[mt][nt][0] + x0.x*dsk;
            yd0.y += e0*acc[mt][nt][1] + x0.y*dsk;
            yd1.x += e1*acc[mt][nt][2] + x1.x*dsk;
            yd1.y += e1*acc[mt][nt][3] + x1.y*dsk;
            *(float2*)yo0 = yd0;
            *(float2*)yo1 = yd1;
        }
    }
}

// ---------------- K11: gated RMSNorm over D_INNER=2048 (half output) ----------------
__global__ __launch_bounds__(256) void gatenorm_kernel(const float* __restrict__ y,
                                                       const float* __restrict__ zx,
                                                       const float* __restrict__ gw,
                                                       __half* __restrict__ out){
    int row = blockIdx.x, t = threadIdx.x;
    const float* yr = y + (size_t)row*DIN;
    const float* zr = zx + (size_t)row*DPROJ;
    float vals[8]; float ss = 0.f;
    #pragma unroll
    for (int i=0;i<2;i++){
        int cbase = (i*256 + t)*4;
        float4 yv = *(const float4*)(yr + cbase);
        float4 zv = *(const float4*)(zr + cbase);
        float a;
        a = yv.x * siluf(zv.x); vals[i*4+0] = a; ss += a*a;
        a = yv.y * siluf(zv.y); vals[i*4+1] = a; ss += a*a;
        a = yv.z * siluf(zv.z); vals[i*4+2] = a; ss += a*a;
        a = yv.w * siluf(zv.w); vals[i*4+3] = a; ss += a*a;
    }
    __shared__ float red[8];
    for (int o=16;o>0;o>>=1) ss += __shfl_down_sync(0xffffffffu, ss, o);
    if ((t&31)==0) red[t>>5] = ss;
    __syncthreads();
    if (t < 32){
        float s2 = (t<8)? red[t] : 0.f;
        for (int o=4;o>0;o>>=1) s2 += __shfl_down_sync(0xffffffffu, s2, o);
        if (t==0) red[0] = s2;
    }
    __syncthreads();
    float scale = rsqrtf(red[0]/(float)DIN + EPSV);
    #pragma unroll
    for (int i=0;i<2;i++){
        int cbase = (i*256 + t)*4;
        float4 wv = *(const float4*)(gw + cbase);
        __half2 hs[2];
        hs[0] = __floats2half2_rn(vals[i*4+0]*scale*wv.x, vals[i*4+1]*scale*wv.y);
        hs[1] = __floats2half2_rn(vals[i*4+2]*scale*wv.z, vals[i*4+3]*scale*wv.w);
        *(uint2*)(out + (size_t)row*DIN + cbase) = *(uint2*)hs;
    }
}

// ---------------- launch ----------------
extern "C" void kernel_launch(void* const* d_in, const int* in_sizes, int n_in,
                              void* d_out, int out_size){
    const float* hidden  = (const float*)d_in[0];
    const float* norm_w  = (const float*)d_in[1];
    const float* in_proj = (const float*)d_in[2];
    const float* conv_w  = (const float*)d_in[3];
    const float* conv_b  = (const float*)d_in[4];
    const float* dt_bias = (const float*)d_in[5];
    const float* A_log   = (const float*)d_in[6];
    const float* Dsk     = (const float*)d_in[7];
    const float* gnw     = (const float*)d_in[8];
    const float* out_w   = (const float*)d_in[9];
    float* out = (float*)d_out;

    float *p_zx, *p_dtv, *p_acum, *p_states, *p_prevS, *p_ydiag;
    __half *p_xh, *p_xbch, *p_ygh, *p_wAh, *p_wBh, *p_gh;
    cudaGetSymbolAddress((void**)&p_xh,    g_xh);
    cudaGetSymbolAddress((void**)&p_zx,    g_zxbcdt);
    cudaGetSymbolAddress((void**)&p_xbch,  g_xBCh);
    cudaGetSymbolAddress((void**)&p_dtv,   g_dtv);
    cudaGetSymbolAddress((void**)&p_acum,  g_Acum);
    cudaGetSymbolAddress((void**)&p_gh,    g_Gh);
    cudaGetSymbolAddress((void**)&p_states,g_states);
    cudaGetSymbolAddress((void**)&p_prevS, g_prevS);
    cudaGetSymbolAddress((void**)&p_ydiag, g_ydiag);
    cudaGetSymbolAddress((void**)&p_ygh,   g_ygh);
    cudaGetSymbolAddress((void**)&p_wAh,   g_wAh);
    cudaGetSymbolAddress((void**)&p_wBh,   g_wBh);

    cudaFuncSetAttribute(h16gemm_kernel, cudaFuncAttributeMaxDynamicSharedMemorySize, GEMM_SMEM);
    cudaFuncSetAttribute(gmat_h_kernel,  cudaFuncAttributeMaxDynamicSharedMemorySize, GM_SMEM);
    cudaFuncSetAttribute(ydiag_h_kernel, cudaFuncAttributeMaxDynamicSharedMemorySize, YD_SMEM);
    cudaFuncSetAttribute(states_h_kernel,cudaFuncAttributeMaxDynamicSharedMemorySize, ST_SMEM);
    cudaFuncSetAttribute(yoff_h_kernel,  cudaFuncAttributeMaxDynamicSharedMemorySize, YO_SMEM);

    // 0. convert weights to half
    f2h_kernel<<<(DM*DPROJ/4 + 255)/256, 256>>>(in_proj, p_wAh, DM*DPROJ/4);
    f2h_kernel<<<(DIN*DM/4 + 255)/256, 256>>>(out_w, p_wBh, DIN*DM/4);
    // 1. RMSNorm (emits half)
    rmsnorm_kernel<<<NTOK, 256>>>(hidden, norm_w, p_xh);
    // 2. in_proj GEMM (fp16 tensor cores)
    h16gemm_kernel<<<dim3((DPROJ+127)/128, NTOK/128), 256, GEMM_SMEM>>>(NTOK, DPROJ, DM, p_xh, p_wAh, nullptr, p_zx);
    // 3. conv1d + bias + silu (emits half, 2 ch/thread)
    conv_kernel<<<(NTOK*CONVDIM/2 + 255)/256, 256>>>(p_zx, conv_w, conv_b, p_xbch);
    // 4. dt softplus
    dt_kernel<<<(NTOK*NH + 255)/256, 256>>>(p_zx, dt_bias, p_dtv);
    // 5. per-chunk cumsum
    cumsum_kernel<<<BB*NCHK*NH, 256>>>(p_dtv, A_log, p_acum);
    // 6. G = C·B^T (fp16 MMA, half in/out)
    gmat_h_kernel<<<dim3(2,2,BB*NCHK), 256, GM_SMEM>>>(p_xbch, p_gh);
    // 7. Y_diag (fp16 MMA)
    ydiag_h_kernel<<<BB*NCHK*NH, 256, YD_SMEM>>>(p_xbch, p_dtv, p_acum, p_gh, p_ydiag);
    // 8. chunk states (fp16 MMA)
    states_h_kernel<<<BB*NCHK*NH, 256, ST_SMEM>>>(p_xbch, p_dtv, p_acum, p_states);
    // 9. inter-chunk scan
    scan_kernel<<<(BB*NH*HD*DS + 255)/256, 256>>>(p_states, p_acum, p_prevS);
    // 10. Y_off (fp16 MMA) + combine + D skip
    yoff_h_kernel<<<BB*NCHK*NH, 256, YO_SMEM>>>(p_xbch, p_acum, p_prevS, Dsk, p_ydiag);
    // 11. gated RMSNorm (emits half)
    gatenorm_kernel<<<NTOK, 256>>>(p_ydiag, p_zx, gnw, p_ygh);
    // 12. out_proj GEMM (fp16) + residual
    h16gemm_kernel<<<dim3(DM/128, NTOK/128), 256, GEMM_SMEM>>>(NTOK, DM, DIN, p_ygh, p_wBh, hidden, out);
}

// round 14
// speedup vs baseline: 1.2238x; 1.0816x over previous
#include <cuda_runtime.h>
#include <cuda_fp16.h>
#include <math.h>
#include <stdint.h>

// ---------------- problem constants ----------------
#define BB 2
#define LL 4096
#define DM 1024
#define DIN 2048
#define NH 32
#define HD 64
#define DS 128
#define CHUNKSZ 256
#define NCHK 16
#define CONVDIM 2304        // DIN + 2*DS
#define DPROJ 4384          // 2*DIN + 2*DS + NH
#define NTOK (BB*LL)        // 8192
#define EPSV 1e-5f

// ---------------- scratch (device globals; no allocs allowed) ----------------
__device__ __half g_xh[(size_t)NTOK*DM];                // rmsnorm output (half)
__device__ float g_zxbcdt[(size_t)NTOK*DPROJ];
__device__ __half g_xBCh[(size_t)NTOK*CONVDIM];         // conv output (half)
__device__ float g_dtv[(size_t)NTOK*NH];
__device__ float g_Acum[(size_t)BB*NCHK*NH*CHUNKSZ];
__device__ __half g_Gh[(size_t)BB*NCHK*CHUNKSZ*CHUNKSZ];  // G in half
__device__ float g_states[(size_t)BB*NCHK*NH*HD*DS];
__device__ float g_prevS[(size_t)BB*NCHK*NH*HD*DS];
__device__ float g_ydiag[(size_t)NTOK*DIN];             // also final y (in place)
__device__ __half g_ygh[(size_t)NTOK*DIN];              // gatenorm output (half)
__device__ __half g_wAh[(size_t)DM*DPROJ];              // half in_proj_w
__device__ __half g_wBh[(size_t)DIN*DM];                // half out_proj_w

__device__ __forceinline__ float siluf(float x){ return x / (1.f + __expf(-x)); }

__device__ __forceinline__ uint32_t smem_u32(const void* p){
    uint32_t a;
    asm("{ .reg .u64 t; cvta.to.shared.u64 t, %1; cvt.u32.u64 %0, t; }" : "=r"(a) : "l"(p));
    return a;
}

__device__ __forceinline__ void cpa16(uint32_t dst, const void* src, bool pred){
    int sz = pred ? 16 : 0;
    asm volatile("cp.async.cg.shared.global [%0], [%1], 16, %2;" :: "r"(dst), "l"(src), "r"(sz));
}

#define CP_COMMIT() asm volatile("cp.async.commit_group;")
#define CP_WAIT2()  asm volatile("cp.async.wait_group 2;")

#define LDSM4(r0,r1,r2,r3,addr) \
    asm volatile("ldmatrix.sync.aligned.m8n8.x4.shared.b16 {%0,%1,%2,%3}, [%4];" \
        : "=r"(r0),"=r"(r1),"=r"(r2),"=r"(r3) : "r"(addr))

#define LDSM4T(r0,r1,r2,r3,addr) \
    asm volatile("ldmatrix.sync.aligned.m8n8.x4.trans.shared.b16 {%0,%1,%2,%3}, [%4];" \
        : "=r"(r0),"=r"(r1),"=r"(r2),"=r"(r3) : "r"(addr))

#define MMA_F16(c, a, b) \
    asm volatile("mma.sync.aligned.m16n8k16.row.col.f32.f16.f16.f32 " \
        "{%0,%1,%2,%3}, {%4,%5,%6,%7}, {%8,%9}, {%0,%1,%2,%3};" \
        : "+f"((c)[0]),"+f"((c)[1]),"+f"((c)[2]),"+f"((c)[3]) \
        : "r"((a)[0]),"r"((a)[1]),"r"((a)[2]),"r"((a)[3]), "r"((b)[0]),"r"((b)[1]))

// ---------------- K0: convert fp32 array to half ----------------
__global__ void f2h_kernel(const float* __restrict__ in, __half* __restrict__ out, int n4){
    int i = blockIdx.x*blockDim.x + threadIdx.x;
    if (i >= n4) return;
    float4 v = ((const float4*)in)[i];
    __half2 hs[2];
    hs[0] = __floats2half2_rn(v.x, v.y);
    hs[1] = __floats2half2_rn(v.z, v.w);
    *(uint2*)(out + (size_t)i*4) = *(uint2*)hs;
}

// ---------------- K1: RMSNorm over D_MODEL=1024 (half output) ----------------
__global__ __launch_bounds__(256) void rmsnorm_kernel(const float* __restrict__ x,
                                                      const float* __restrict__ w,
                                                      __half* __restrict__ out){
    int row = blockIdx.x;
    int t = threadIdx.x;
    float4 v = ((const float4*)(x + (size_t)row*DM))[t];
    float ss = v.x*v.x + v.y*v.y + v.z*v.z + v.w*v.w;
    __shared__ float red[8];
    for (int o=16;o>0;o>>=1) ss += __shfl_down_sync(0xffffffffu, ss, o);
    if ((t&31)==0) red[t>>5] = ss;
    __syncthreads();
    if (t < 32){
        float s2 = (t<8)? red[t] : 0.f;
        for (int o=4;o>0;o>>=1) s2 += __shfl_down_sync(0xffffffffu, s2, o);
        if (t==0) red[0] = s2;
    }
    __syncthreads();
    float scale = rsqrtf(red[0]/(float)DM + EPSV);
    float4 wv = ((const float4*)w)[t];
    __half2 hs[2];
    hs[0] = __floats2half2_rn(v.x*scale*wv.x, v.y*scale*wv.y);
    hs[1] = __floats2half2_rn(v.z*scale*wv.z, v.w*scale*wv.w);
    *(uint2*)(out + (size_t)row*DM + t*4) = *(uint2*)hs;
}

// ---------------- FP16 GEMM: 128x128 block, BK=32, 4-stage cp.async, 2 CTAs/SM ----
#define AH_STRIDE 40
#define BH_STRIDE 136
#define ASTG_H (128*AH_STRIDE)
#define BSTG_H (32*BH_STRIDE)
#define NSTAGE 4
#define GEMM_SMEM ((NSTAGE*(ASTG_H + BSTG_H))*2)

__global__ __launch_bounds__(256, 2) void h16gemm_kernel(int M, int N, int K,
                                                         const __half* __restrict__ A,
                                                         const __half* __restrict__ B,
                                                         const float* __restrict__ Cadd,
                                                         float* __restrict__ C){
    extern __shared__ __half hsmem[];
    __half* As = hsmem;
    __half* Bs = hsmem + NSTAGE*ASTG_H;
    uint32_t aSm = smem_u32(As);
    uint32_t bSm = smem_u32(Bs);

    int tid = threadIdx.x, lane = tid & 31, warp = tid >> 5;
    int warpM = warp & 1, warpN = warp >> 1;
    int gid = lane >> 2, tg = lane & 3;
    int lr = lane & 7, ls = lane >> 3;
    int rowBlk = blockIdx.y*128, colBase = blockIdx.x*128;

    int aRow = tid >> 1, aKc = (tid & 1)*16;
    int bK = tid >> 3, bN = (tid & 7)*16;

    const __half* Ag = A + (size_t)(rowBlk + aRow)*K + aKc;
    const __half* Bg = B + (size_t)bK*N + colBase + bN;
    bool p0 = (colBase + bN) < N;
    bool p1 = (colBase + bN + 8) < N;

    float acc[4][4][4] = {};
    int KT = K >> 5;

    #pragma unroll
    for (int s=0; s<3; s++){
        uint32_t ad = aSm + (uint32_t)(s*ASTG_H + aRow*AH_STRIDE + aKc)*2;
        const __half* ap = Ag + s*32;
        cpa16(ad, ap, true);
        cpa16(ad+16, ap+8, true);
        uint32_t bd = bSm + (uint32_t)(s*BSTG_H + bK*BH_STRIDE + bN)*2;
        const __half* bpp = Bg + (size_t)s*32*N;
        cpa16(bd, p0 ? bpp : B, p0);
        cpa16(bd+16, p1 ? bpp+8 : B, p1);
        CP_COMMIT();
    }

    for (int kt=0; kt<KT; kt++){
        int s = kt % NSTAGE;
        CP_WAIT2();
        __syncthreads();
        if (kt+3 < KT){
            int s2 = (kt+3) % NSTAGE;
            uint32_t ad = aSm + (uint32_t)(s2*ASTG_H + aRow*AH_STRIDE + aKc)*2;
            const __half* ap = Ag + (kt+3)*32;
            cpa16(ad, ap, true);
            cpa16(ad+16, ap+8, true);
            uint32_t bd = bSm + (uint32_t)(s2*BSTG_H + bK*BH_STRIDE + bN)*2;
            const __half* bpp = Bg + (size_t)(kt+3)*32*N;
            cpa16(bd, p0 ? bpp : B, p0);
            cpa16(bd+16, p1 ? bpp+8 : B, p1);
        }
        CP_COMMIT();

        uint32_t aBase = aSm + (uint32_t)(s*ASTG_H)*2;
        uint32_t bBase = bSm + (uint32_t)(s*BSTG_H)*2;
        #pragma unroll
        for (int kk=0; kk<2; kk++){
            int kc = kk*16;
            uint32_t af[4][4], bf[4][2];
            #pragma unroll
            for (int mt=0;mt<4;mt++){
                int m0 = warpM*64 + mt*16;
                uint32_t addr = aBase + (uint32_t)((m0 + (ls&1)*8 + lr)*AH_STRIDE + kc + (ls>>1)*8)*2;
                LDSM4(af[mt][0], af[mt][1], af[mt][2], af[mt][3], addr);
            }
            #pragma unroll
            for (int ntp=0;ntp<2;ntp++){
                int n0 = warpN*32 + ntp*16;
                uint32_t addr = bBase + (uint32_t)((kc + (ls&1)*8 + lr)*BH_STRIDE + n0 + (ls>>1)*8)*2;
                uint32_t r0,r1,r2,r3;
                LDSM4T(r0,r1,r2,r3, addr);
                bf[2*ntp][0]=r0; bf[2*ntp][1]=r1;
                bf[2*ntp+1][0]=r2; bf[2*ntp+1][1]=r3;
            }
            #pragma unroll
            for (int mt=0;mt<4;mt++)
                #pragma unroll
                for (int nt=0;nt<4;nt++)
                    MMA_F16(acc[mt][nt], af[mt], bf[nt]);
        }
    }

    #pragma unroll
    for (int mt=0;mt<4;mt++){
        int row0 = rowBlk + warpM*64 + mt*16 + gid;
        #pragma unroll
        for (int nt=0;nt<4;nt++){
            int col = colBase + warpN*32 + nt*8 + tg*2;
            if (col < N){
                float2 v0 = make_float2(acc[mt][nt][0], acc[mt][nt][1]);
                float2 v1 = make_float2(acc[mt][nt][2], acc[mt][nt][3]);
                if (Cadd){
                    float2 r0 = *(const float2*)(Cadd + (size_t)row0*N + col);
                    float2 r1 = *(const float2*)(Cadd + (size_t)(row0+8)*N + col);
                    v0.x += r0.x; v0.y += r0.y;
                    v1.x += r1.x; v1.y += r1.y;
                }
                *(float2*)(C + (size_t)row0*N + col) = v0;
                *(float2*)(C + (size_t)(row0+8)*N + col) = v1;
            }
        }
    }
}

// ---------------- K3: conv1d, 4 rows x 2 channels per thread (half out) ----------
__global__ void conv_kernel(const float* __restrict__ zx, const float* __restrict__ cw,
                            const float* __restrict__ cb, __half* __restrict__ out){
    int idx = blockIdx.x*blockDim.x + threadIdx.x;
    if (idx >= (NTOK/4)*(CONVDIM/2)) return;
    int cpair = idx % (CONVDIM/2);
    int rowq = idx / (CONVDIM/2);
    int c = cpair*2;
    int base = rowq*4;
    int l0 = base & (LL-1);          // rows base..base+3 share a sequence (LL%4==0)

    float2 v[7];
    #pragma unroll
    for (int j=0;j<7;j++){
        int ls = l0 - 3 + j;
        v[j] = (ls >= 0) ? *(const float2*)(zx + (size_t)(base-3+j)*DPROJ + DIN + c)
                         : make_float2(0.f, 0.f);
    }
    float w0[4], w1[4];
    #pragma unroll
    for (int k=0;k<4;k++){ w0[k] = cw[c*4+k]; w1[k] = cw[(c+1)*4+k]; }
    float b0 = cb[c], b1 = cb[c+1];

    #pragma unroll
    for (int r=0;r<4;r++){
        float a0 = b0, a1 = b1;
        #pragma unroll
        for (int k=0;k<4;k++){
            a0 += v[r+k].x * w0[k];
            a1 += v[r+k].y * w1[k];
        }
        *(__half2*)(out + (size_t)(base+r)*CONVDIM + c) = __floats2half2_rn(siluf(a0), siluf(a1));
    }
}

// ---------------- K4: dt = softplus(dt_raw + dt_bias) ----------------
__global__ void dt_kernel(const float* __restrict__ zx, const float* __restrict__ dt_bias,
                          float* __restrict__ dtv){
    int idx = blockIdx.x*blockDim.x + threadIdx.x;
    if (idx >= NTOK*NH) return;
    int h = idx & (NH-1);
    int row = idx / NH;
    float x = zx[(size_t)row*DPROJ + (DIN + CONVDIM) + h] + dt_bias[h];
    dtv[idx] = (x > 20.f) ? x : log1pf(expf(x));
}

// ---------------- K5: per-(b,c,h) inclusive cumsum of dt*A over chunk ----------------
__global__ __launch_bounds__(256) void cumsum_kernel(const float* __restrict__ dtv,
                                                     const float* __restrict__ A_log,
                                                     float* __restrict__ Acum){
    int bid = blockIdx.x;
    int h = bid % NH; int c = (bid/NH) % NCHK; int b = bid/(NH*NCHK);
    int t = threadIdx.x;
    int row = b*LL + c*CHUNKSZ + t;
    float negA = -expf(A_log[h]);
    float v = dtv[(size_t)row*NH + h] * negA;
    __shared__ float sh[256];
    sh[t] = v; __syncthreads();
    for (int off=1; off<256; off<<=1){
        float add = (t >= off) ? sh[t-off] : 0.f;
        __syncthreads();
        sh[t] += add;
        __syncthreads();
    }
    Acum[(size_t)bid*CHUNKSZ + t] = sh[t];
}

// ---------------- K6: gmat fp16 MMA: G = C·B^T per (b,c), half in/out ----------
#define GM_SMEM (2*128*136*2)
__global__ __launch_bounds__(256) void gmat_h_kernel(const __half* __restrict__ xbc,
                                                     __half* __restrict__ Gh){
    extern __shared__ __half hsm[];
    __half* Ct = hsm;
    __half* Bt = hsm + 128*136;
    uint32_t ctSm = smem_u32(Ct), btSm = smem_u32(Bt);

    int bc = blockIdx.z;
    int b = bc / NCHK, c = bc % NCHK;
    int lt = blockIdx.x*128, st = blockIdx.y*128;
    int rowbase = b*LL + c*CHUNKSZ;
    int t = threadIdx.x, lane = t & 31, warp = t >> 5;
    int wl = warp & 1, wn = warp >> 1;
    int gid = lane >> 2, tg = lane & 3;
    int lr = lane & 7, lsm = lane >> 3;

    #pragma unroll 4
    for (int i=0;i<32;i++){
        int f = i*256 + t; int r = f >> 6, cp = (f & 63)*2;
        *(__half2*)&Ct[r*136+cp] = *(const __half2*)(xbc + (size_t)(rowbase+lt+r)*CONVDIM + 2176 + cp);
        *(__half2*)&Bt[r*136+cp] = *(const __half2*)(xbc + (size_t)(rowbase+st+r)*CONVDIM + 2048 + cp);
    }
    __syncthreads();

    float acc[4][4][4] = {};
    #pragma unroll
    for (int kk=0; kk<8; kk++){
        int kc = kk*16;
        uint32_t af[4][4], bf[4][2];
        #pragma unroll
        for (int mt=0;mt<4;mt++){
            uint32_t addr = ctSm + (uint32_t)((wl*64+mt*16 + (lsm&1)*8 + lr)*136 + kc + (lsm>>1)*8)*2;
            LDSM4(af[mt][0], af[mt][1], af[mt][2], af[mt][3], addr);
        }
        #pragma unroll
        for (int g=0;g<2;g++){
            uint32_t addr = btSm + (uint32_t)((wn*32+g*16 + (lsm&1)*8 + lr)*136 + kc + (lsm>>1)*8)*2;
            uint32_t r0,r1,r2,r3;
            LDSM4(r0,r1,r2,r3, addr);
            bf[2*g][0]=r0; bf[2*g+1][0]=r1; bf[2*g][1]=r2; bf[2*g+1][1]=r3;
        }
        #pragma unroll
        for (int mt=0;mt<4;mt++)
            #pragma unroll
            for (int nt=0;nt<4;nt++)
                MMA_F16(acc[mt][nt], af[mt], bf[nt]);
    }

    #pragma unroll
    for (int mt=0;mt<4;mt++){
        int l0 = lt + wl*64 + mt*16 + gid;
        #pragma unroll
        for (int nt=0;nt<4;nt++){
            int s0 = st + wn*32 + nt*8 + tg*2;
            *(__half2*)(Gh + ((size_t)bc*CHUNKSZ + l0)*CHUNKSZ + s0) =
                __floats2half2_rn(acc[mt][nt][0], acc[mt][nt][1]);
            *(__half2*)(Gh + ((size_t)bc*CHUNKSZ + l0 + 8)*CHUNKSZ + s0) =
                __floats2half2_rn(acc[mt][nt][2], acc[mt][nt][3]);
        }
    }
}

// ---------------- K7: Y_diag fp16 MMA per (b,c,h), two-table exp ----------------
#define YD_SMEM (256*72*2 + 64*72*2 + 256*4 + 64*4 + 1024*4 + 64*4)
__global__ __launch_bounds__(256) void ydiag_h_kernel(const __half* __restrict__ xbc,
                                                      const float* __restrict__ dtv,
                                                      const float* __restrict__ Acum,
                                                      const __half* __restrict__ Gh,
                                                      float* __restrict__ ydiag){
    extern __shared__ __half hsm[];
    __half* Mh = hsm;                 // [256 l][72]
    __half* Xh = hsm + 256*72;        // [64 s][72] (cols = p)
    float* aL  = (float*)(hsm + 256*72 + 64*72);
    float* dts = aL + 256;
    float* E1s = dts + 64;            // [256 row][4 g]
    float* E2s = E1s + 1024;          // [64 col]
    uint32_t mSm = smem_u32(Mh), xSm = smem_u32(Xh);

    int bid = blockIdx.x;
    int h = bid % NH; int c = (bid/NH) % NCHK; int b = bid/(NH*NCHK);
    int bc = b*NCHK + c;
    int rowbase = b*LL + c*CHUNKSZ;
    int t = threadIdx.x, lane = t & 31, warp = t >> 5;
    int wl = warp >> 1, wp = warp & 1;     // 4(l) x 2(p)
    int gid = lane >> 2, tg = lane & 3;
    int lr = lane & 7, lsm = lane >> 3;
    const __half* Gb = Gh + (size_t)bc*CHUNKSZ*CHUNKSZ;

    aL[t] = Acum[(size_t)bid*CHUNKSZ + t];
    float acc[4][4][4] = {};

    for (int sb=0; sb<4; sb++){
        int s0 = sb*64;
        __syncthreads();
        if (t < 64){
            dts[t] = dtv[(size_t)(rowbase+s0+t)*NH + h];
            // E2[col] = exp(a_ref(g) - aL[s0+col]),  ref(g)=s0+16*(col/16)
            E2s[t] = __expf(aL[s0 + (t & 48)] - aL[s0 + t]);
        }
        __syncthreads();
        // E1[row][g] = exp(aL[row] - aL[s0+16g])  (only used where row >= s0+16g)
        {
            float a_row = aL[t];
            #pragma unroll
            for (int g=0; g<4; g++)
                E1s[t*4+g] = __expf(a_row - aL[s0 + g*16]);
        }
        __syncthreads();
        // M tile [256 l][64 s] = tril(G)·E1·E2
        #pragma unroll 4
        for (int i=0;i<64;i++){
            int f = i*256 + t; int row = f >> 6, col = f & 63;
            int sg = s0 + col;
            __half val = __float2half_rn(0.f);
            if (sg <= row){
                float gv = __half2float(Gb[(size_t)row*CHUNKSZ + sg]);
                val = __float2half_rn(gv * (E1s[row*4 + (col>>4)] * E2s[col]));
            }
            Mh[row*72+col] = val;
        }
        // Xd tile [64 s][64 p] = x * dt
        #pragma unroll 4
        for (int i=0;i<16;i++){
            int f = i*256 + t; int row = f >> 6, col = f & 63;
            float xv = __half2float(xbc[(size_t)(rowbase+s0+row)*CONVDIM + h*HD + col]);
            Xh[row*72+col] = __float2half_rn(xv * dts[row]);
        }
        __syncthreads();
        if (sb <= wl){
            #pragma unroll
            for (int kk=0; kk<4; kk++){
                int kc = kk*16;
                uint32_t af[4][4], bf[4][2];
                #pragma unroll
                for (int mt=0;mt<4;mt++){
                    uint32_t addr = mSm + (uint32_t)((wl*64+mt*16 + (lsm&1)*8 + lr)*72 + kc + (lsm>>1)*8)*2;
                    LDSM4(af[mt][0], af[mt][1], af[mt][2], af[mt][3], addr);
                }
                #pragma unroll
                for (int g=0;g<2;g++){
                    uint32_t addr = xSm + (uint32_t)((kc + (lsm&1)*8 + lr)*72 + wp*32 + g*16 + (lsm>>1)*8)*2;
                    uint32_t r0,r1,r2,r3;
                    LDSM4T(r0,r1,r2,r3, addr);
                    bf[2*g][0]=r0; bf[2*g][1]=r1; bf[2*g+1][0]=r2; bf[2*g+1][1]=r3;
                }
                #pragma unroll
                for (int mt=0;mt<4;mt++)
                    #pragma unroll
                    for (int nt=0;nt<4;nt++)
                        MMA_F16(acc[mt][nt], af[mt], bf[nt]);
            }
        }
    }

    #pragma unroll
    for (int mt=0;mt<4;mt++){
        int l0 = wl*64 + mt*16 + gid;
        #pragma unroll
        for (int nt=0;nt<4;nt++){
            int p0 = wp*32 + nt*8 + tg*2;
            *(float2*)(ydiag + (size_t)(rowbase+l0)*DIN + h*HD + p0) =
                make_float2(acc[mt][nt][0], acc[mt][nt][1]);
            *(float2*)(ydiag + (size_t)(rowbase+l0+8)*DIN + h*HD + p0) =
                make_float2(acc[mt][nt][2], acc[mt][nt][3]);
        }
    }
}

// ---------------- K8: states fp16 MMA per (b,c,h): S[p,n] ----------------
#define ST_SMEM (128*72*2 + 128*136*2 + 128*4)
__global__ __launch_bounds__(256) void states_h_kernel(const __half* __restrict__ xbc,
                                                       const float* __restrict__ dtv,
                                                       const float* __restrict__ Acum,
                                                       float* __restrict__ states){
    extern __shared__ __half hsm[];
    __half* Xc = hsm;
    __half* Bt = hsm + 128*72;
    float* cl = (float*)(hsm + 128*72 + 128*136);
    uint32_t xSm = smem_u32(Xc), bSm = smem_u32(Bt);

    int bid = blockIdx.x;
    int h = bid % NH; int c = (bid/NH) % NCHK; int b = bid/(NH*NCHK);
    int rowbase = b*LL + c*CHUNKSZ;
    int t = threadIdx.x, lane = t & 31, warp = t >> 5;
    int wm = warp & 1, wn = warp >> 1;
    int gid = lane >> 2, tg = lane & 3;
    int lr = lane & 7, lsm = lane >> 3;

    float Atot = Acum[(size_t)bid*CHUNKSZ + 255];
    float acc[2][4][4] = {};

    for (int ch=0; ch<2; ch++){
        int l0 = ch*128;
        __syncthreads();
        if (t < 128){
            int l = l0 + t;
            cl[t] = dtv[(size_t)(rowbase+l)*NH + h] * __expf(Atot - Acum[(size_t)bid*CHUNKSZ + l]);
        }
        __syncthreads();
        #pragma unroll 4
        for (int i=0;i<32;i++){
            int f = i*256 + t; int row = f >> 6, col = f & 63;
            float xv = __half2float(xbc[(size_t)(rowbase+l0+row)*CONVDIM + h*HD + col]);
            Xc[row*72+col] = __float2half_rn(xv * cl[row]);
        }
        #pragma unroll 4
        for (int i=0;i<32;i++){
            int f = i*256 + t; int row = f >> 6, cp = (f & 63)*2;
            *(__half2*)&Bt[row*136+cp] = *(const __half2*)(xbc + (size_t)(rowbase+l0+row)*CONVDIM + 2048 + cp);
        }
        __syncthreads();
        #pragma unroll
        for (int kk=0; kk<8; kk++){
            int kc = kk*16;
            uint32_t af[2][4], bf[4][2];
            #pragma unroll
            for (int mt=0;mt<2;mt++){
                uint32_t addr = xSm + (uint32_t)((kc + (lsm&1)*8 + lr)*72 + wm*32 + mt*16 + (lsm>>1)*8)*2;
                uint32_t r0,r1,r2,r3;
                LDSM4T(r0,r1,r2,r3, addr);
                af[mt][0]=r0; af[mt][1]=r2; af[mt][2]=r1; af[mt][3]=r3;
            }
            #pragma unroll
            for (int g=0;g<2;g++){
                uint32_t addr = bSm + (uint32_t)((kc + (lsm&1)*8 + lr)*136 + wn*32 + g*16 + (lsm>>1)*8)*2;
                uint32_t r0,r1,r2,r3;
                LDSM4T(r0,r1,r2,r3, addr);
                bf[2*g][0]=r0; bf[2*g][1]=r1; bf[2*g+1][0]=r2; bf[2*g+1][1]=r3;
            }
            #pragma unroll
            for (int mt=0;mt<2;mt++)
                #pragma unroll
                for (int nt=0;nt<4;nt++)
                    MMA_F16(acc[mt][nt], af[mt], bf[nt]);
        }
    }

    #pragma unroll
    for (int mt=0;mt<2;mt++){
        int p0 = wm*32 + mt*16 + gid;
        #pragma unroll
        for (int nt=0;nt<4;nt++){
            int n0 = wn*32 + nt*8 + tg*2;
            *(float2*)(states + ((size_t)bid*HD + p0)*DS + n0) =
                make_float2(acc[mt][nt][0], acc[mt][nt][1]);
            *(float2*)(states + ((size_t)bid*HD + p0 + 8)*DS + n0) =
                make_float2(acc[mt][nt][2], acc[mt][nt][3]);
        }
    }
}

// ---------------- K9: inter-chunk scan ----------------
__global__ void scan_kernel(const float* __restrict__ states, const float* __restrict__ Acum,
                            float* __restrict__ prevS){
    int idx = blockIdx.x*blockDim.x + threadIdx.x;
    if (idx >= BB*NH*HD*DS) return;
    int n = idx & 127;
    int p = (idx >> 7) & 63;
    int h = (idx >> 13) & 31;
    int b = idx >> 18;
    float S = 0.f;
    for (int c=0;c<NCHK;c++){
        int bid = (b*NCHK + c)*NH + h;
        size_t off = ((size_t)bid*HD + p)*DS + n;
        prevS[off] = S;
        float T = Acum[(size_t)bid*CHUNKSZ + 255];
        S = expf(T)*S + states[off];
    }
}

// ---------------- K10: Y_off fp16 MMA + combine (in place into ydiag) ----------
#define YO_SMEM (256*136*2 + 64*136*2 + 256*4)
__global__ __launch_bounds__(256) void yoff_h_kernel(const __half* __restrict__ xbc,
                                                     const float* __restrict__ Acum,
                                                     const float* __restrict__ prevS,
                                                     const float* __restrict__ Dskip,
                                                     float* __restrict__ y){
    extern __shared__ __half hsm[];
    __half* Ct = hsm;
    __half* St = hsm + 256*136;
    float* eL = (float*)(hsm + 256*136 + 64*136);
    uint32_t cSm = smem_u32(Ct), sSm = smem_u32(St);

    int bid = blockIdx.x;
    int h = bid % NH; int c = (bid/NH) % NCHK; int b = bid/(NH*NCHK);
    int rowbase = b*LL + c*CHUNKSZ;
    int t = threadIdx.x, lane = t & 31, warp = t >> 5;
    int wl = warp >> 1, wp = warp & 1;
    int gid = lane >> 2, tg = lane & 3;
    int lr = lane & 7, lsm = lane >> 3;
    const float* Sb = prevS + (size_t)bid*HD*DS;

    eL[t] = __expf(Acum[(size_t)bid*CHUNKSZ + t]);
    #pragma unroll 4
    for (int i=0;i<64;i++){
        int f = i*256 + t; int row = f >> 6, cp = (f & 63)*2;
        *(__half2*)&Ct[row*136+cp] = *(const __half2*)(xbc + (size_t)(rowbase+row)*CONVDIM + 2176 + cp);
    }
    #pragma unroll 4
    for (int i=0;i<16;i++){
        int f = i*256 + t; int row = f >> 6, cp = (f & 63)*2;
        float2 sv = *(const float2*)(Sb + (size_t)row*DS + cp);
        *(__half2*)&St[row*136+cp] = __floats2half2_rn(sv.x, sv.y);
    }
    __syncthreads();

    float acc[4][4][4] = {};
    #pragma unroll
    for (int kk=0; kk<8; kk++){
        int kc = kk*16;
        uint32_t af[4][4], bf[4][2];
        #pragma unroll
        for (int mt=0;mt<4;mt++){
            uint32_t addr = cSm + (uint32_t)((wl*64+mt*16 + (lsm&1)*8 + lr)*136 + kc + (lsm>>1)*8)*2;
            LDSM4(af[mt][0], af[mt][1], af[mt][2], af[mt][3], addr);
        }
        #pragma unroll
        for (int g=0;g<2;g++){
            uint32_t addr = sSm + (uint32_t)((wp*32+g*16 + (lsm&1)*8 + lr)*136 + kc + (lsm>>1)*8)*2;
            uint32_t r0,r1,r2,r3;
            LDSM4(r0,r1,r2,r3, addr);
            bf[2*g][0]=r0; bf[2*g+1][0]=r1; bf[2*g][1]=r2; bf[2*g+1][1]=r3;
        }
        #pragma unroll
        for (int mt=0;mt<4;mt++)
            #pragma unroll
            for (int nt=0;nt<4;nt++)
                MMA_F16(acc[mt][nt], af[mt], bf[nt]);
    }

    float dsk = Dskip[h];
    #pragma unroll
    for (int mt=0;mt<4;mt++){
        int l0 = wl*64 + mt*16 + gid;
        float e0 = eL[l0], e1 = eL[l0+8];
        #pragma unroll
        for (int nt=0;nt<4;nt++){
            int p0 = wp*32 + nt*8 + tg*2;
            float* yo0 = y + (size_t)(rowbase+l0)*DIN + h*HD + p0;
            float* yo1 = y + (size_t)(rowbase+l0+8)*DIN + h*HD + p0;
            float2 yd0 = *(float2*)yo0, yd1 = *(float2*)yo1;
            __half2 xh0 = *(const __half2*)(xbc + (size_t)(rowbase+l0)*CONVDIM + h*HD + p0);
            __half2 xh1 = *(const __half2*)(xbc + (size_t)(rowbase+l0+8)*CONVDIM + h*HD + p0);
            float2 x0 = __half22float2(xh0);
            float2 x1 = __half22float2(xh1);
            yd0.x += e0*acc[mt][nt][0] + x0.x*dsk;
            yd0.y += e0*acc[mt][nt][1] + x0.y*dsk;
            yd1.x += e1*acc[mt][nt][2] + x1.x*dsk;
            yd1.y += e1*acc[mt][nt][3] + x1.y*dsk;
            *(float2*)yo0 = yd0;
            *(float2*)yo1 = yd1;
        }
    }
}

// ---------------- K11: gated RMSNorm over D_INNER=2048 (half output) ----------------
__global__ __launch_bounds__(256) void gatenorm_kernel(const float* __restrict__ y,
                                                       const float* __restrict__ zx,
                                                       const float* __restrict__ gw,
                                                       __half* __restrict__ out){
    int row = blockIdx.x, t = threadIdx.x;
    const float* yr = y + (size_t)row*DIN;
    const float* zr = zx + (size_t)row*DPROJ;
    float vals[8]; float ss = 0.f;
    #pragma unroll
    for (int i=0;i<2;i++){
        int cbase = (i*256 + t)*4;
        float4 yv = *(const float4*)(yr + cbase);
        float4 zv = *(const float4*)(zr + cbase);
        float a;
        a = yv.x * siluf(zv.x); vals[i*4+0] = a; ss += a*a;
        a = yv.y * siluf(zv.y); vals[i*4+1] = a; ss += a*a;
        a = yv.z * siluf(zv.z); vals[i*4+2] = a; ss += a*a;
        a = yv.w * siluf(zv.w); vals[i*4+3] = a; ss += a*a;
    }
    __shared__ float red[8];
    for (int o=16;o>0;o>>=1) ss += __shfl_down_sync(0xffffffffu, ss, o);
    if ((t&31)==0) red[t>>5] = ss;
    __syncthreads();
    if (t < 32){
        float s2 = (t<8)? red[t] : 0.f;
        for (int o=4;o>0;o>>=1) s2 += __shfl_down_sync(0xffffffffu, s2, o);
        if (t==0) red[0] = s2;
    }
    __syncthreads();
    float scale = rsqrtf(red[0]/(float)DIN + EPSV);
    #pragma unroll
    for (int i=0;i<2;i++){
        int cbase = (i*256 + t)*4;
        float4 wv = *(const float4*)(gw + cbase);
        __half2 hs[2];
        hs[0] = __floats2half2_rn(vals[i*4+0]*scale*wv.x, vals[i*4+1]*scale*wv.y);
        hs[1] = __floats2half2_rn(vals[i*4+2]*scale*wv.z, vals[i*4+3]*scale*wv.w);
        *(uint2*)(out + (size_t)row*DIN + cbase) = *(uint2*)hs;
    }
}

// ---------------- launch ----------------
extern "C" void kernel_launch(void* const* d_in, const int* in_sizes, int n_in,
                              void* d_out, int out_size){
    const float* hidden  = (const float*)d_in[0];
    const float* norm_w  = (const float*)d_in[1];
    const float* in_proj = (const float*)d_in[2];
    const float* conv_w  = (const float*)d_in[3];
    const float* conv_b  = (const float*)d_in[4];
    const float* dt_bias = (const float*)d_in[5];
    const float* A_log   = (const float*)d_in[6];
    const float* Dsk     = (const float*)d_in[7];
    const float* gnw     = (const float*)d_in[8];
    const float* out_w   = (const float*)d_in[9];
    float* out = (float*)d_out;

    float *p_zx, *p_dtv, *p_acum, *p_states, *p_prevS, *p_ydiag;
    __half *p_xh, *p_xbch, *p_ygh, *p_wAh, *p_wBh, *p_gh;
    cudaGetSymbolAddress((void**)&p_xh,    g_xh);
    cudaGetSymbolAddress((void**)&p_zx,    g_zxbcdt);
    cudaGetSymbolAddress((void**)&p_xbch,  g_xBCh);
    cudaGetSymbolAddress((void**)&p_dtv,   g_dtv);
    cudaGetSymbolAddress((void**)&p_acum,  g_Acum);
    cudaGetSymbolAddress((void**)&p_gh,    g_Gh);
    cudaGetSymbolAddress((void**)&p_states,g_states);
    cudaGetSymbolAddress((void**)&p_prevS, g_prevS);
    cudaGetSymbolAddress((void**)&p_ydiag, g_ydiag);
    cudaGetSymbolAddress((void**)&p_ygh,   g_ygh);
    cudaGetSymbolAddress((void**)&p_wAh,   g_wAh);
    cudaGetSymbolAddress((void**)&p_wBh,   g_wBh);

    cudaFuncSetAttribute(h16gemm_kernel, cudaFuncAttributeMaxDynamicSharedMemorySize, GEMM_SMEM);
    cudaFuncSetAttribute(gmat_h_kernel,  cudaFuncAttributeMaxDynamicSharedMemorySize, GM_SMEM);
    cudaFuncSetAttribute(ydiag_h_kernel, cudaFuncAttributeMaxDynamicSharedMemorySize, YD_SMEM);
    cudaFuncSetAttribute(states_h_kernel,cudaFuncAttributeMaxDynamicSharedMemorySize, ST_SMEM);
    cudaFuncSetAttribute(yoff_h_kernel,  cudaFuncAttributeMaxDynamicSharedMemorySize, YO_SMEM);

    // 0. convert weights to half
    f2h_kernel<<<(DM*DPROJ/4 + 255)/256, 256>>>(in_proj, p_wAh, DM*DPROJ/4);
    f2h_kernel<<<(DIN*DM/4 + 255)/256, 256>>>(out_w, p_wBh, DIN*DM/4);
    // 1. RMSNorm (emits half)
    rmsnorm_kernel<<<NTOK, 256>>>(hidden, norm_w, p_xh);
    // 2. in_proj GEMM (fp16 tensor cores)
    h16gemm_kernel<<<dim3((DPROJ+127)/128, NTOK/128), 256, GEMM_SMEM>>>(NTOK, DPROJ, DM, p_xh, p_wAh, nullptr, p_zx);
    // 3. conv1d + bias + silu (4 rows x 2 ch per thread, half out)
    conv_kernel<<<((NTOK/4)*(CONVDIM/2) + 255)/256, 256>>>(p_zx, conv_w, conv_b, p_xbch);
    // 4. dt softplus
    dt_kernel<<<(NTOK*NH + 255)/256, 256>>>(p_zx, dt_bias, p_dtv);
    // 5. per-chunk cumsum
    cumsum_kernel<<<BB*NCHK*NH, 256>>>(p_dtv, A_log, p_acum);
    // 6. G = C·B^T (fp16 MMA, half in/out)
    gmat_h_kernel<<<dim3(2,2,BB*NCHK), 256, GM_SMEM>>>(p_xbch, p_gh);
    // 7. Y_diag (fp16 MMA, two-table exp)
    ydiag_h_kernel<<<BB*NCHK*NH, 256, YD_SMEM>>>(p_xbch, p_dtv, p_acum, p_gh, p_ydiag);
    // 8. chunk states (fp16 MMA)
    states_h_kernel<<<BB*NCHK*NH, 256, ST_SMEM>>>(p_xbch, p_dtv, p_acum, p_states);
    // 9. inter-chunk scan
    scan_kernel<<<(BB*NH*HD*DS + 255)/256, 256>>>(p_states, p_acum, p_prevS);
    // 10. Y_off (fp16 MMA) + combine + D skip
    yoff_h_kernel<<<BB*NCHK*NH, 256, YO_SMEM>>>(p_xbch, p_acum, p_prevS, Dsk, p_ydiag);
    // 11. gated RMSNorm (emits half)
    gatenorm_kernel<<<NTOK, 256>>>(p_ydiag, p_zx, gnw, p_ygh);
    // 12. out_proj GEMM (fp16) + residual
    h16gemm_kernel<<<dim3(DM/128, NTOK/128), 256, GEMM_SMEM>>>(NTOK, DM, DIN, p_ygh, p_wBh, hidden, out);
}